// round 8
// baseline (speedup 1.0000x reference)
#include <cuda_runtime.h>
#include <cstdint>

#define N_MAX   50000
#define HDIM    256
#define E_MAX   800000
#define MAXCTX  8

// ---------------------------------------------------------------------------
// Scratch (device globals -- no allocation allowed in kernel_launch)
// ---------------------------------------------------------------------------
__device__ float g_h[N_MAX * HDIM];     // h' = (A @ W) * inv[row]
__device__ float g_agg[N_MAX * HDIM];   // scatter accumulator
__device__ float g_feat[N_MAX * HDIM];  // layer output (feat1 then feat2)
__device__ float g_inv[N_MAX];          // deg, then rsqrt(deg)

// ---------------------------------------------------------------------------
// Degree / normalization
// ---------------------------------------------------------------------------
__global__ void deg_init_kernel(float* deg, int n) {
    int i = blockIdx.x * blockDim.x + threadIdx.x;
    if (i < n) deg[i] = 1.0f;  // self loop
}

__global__ void deg_count_kernel(const int* __restrict__ dst, float* deg, int e) {
    int i = blockIdx.x * blockDim.x + threadIdx.x;
    if (i < e) atomicAdd(&deg[dst[i]], 1.0f);
}

__global__ void inv_sqrt_kernel(float* deg, int n) {
    int i = blockIdx.x * blockDim.x + threadIdx.x;
    if (i < n) deg[i] = rsqrtf(deg[i]);   // deg >= 1 always
}

// ---------------------------------------------------------------------------
// TF32 helpers
// ---------------------------------------------------------------------------
__device__ __forceinline__ uint32_t f2tf(float x) {
    uint32_t r;
    asm("cvt.rna.tf32.f32 %0, %1;" : "=r"(r) : "f"(x));
    return r;
}

__device__ __forceinline__ void mma_tf32(float d[4], const uint32_t a[4],
                                         const uint32_t b[2]) {
    asm volatile(
        "mma.sync.aligned.m16n8k8.row.col.f32.tf32.tf32.f32 "
        "{%0,%1,%2,%3}, {%4,%5,%6,%7}, {%8,%9}, {%0,%1,%2,%3};"
        : "+f"(d[0]), "+f"(d[1]), "+f"(d[2]), "+f"(d[3])
        : "r"(a[0]), "r"(a[1]), "r"(a[2]), "r"(a[3]),
          "r"(b[0]), "r"(b[1]));
}

// Fragment-layout smem addressing (m16n8k8):
//  A element (m local, k local) for BK with KS k-steps:
//    mt=m>>4, r=m&15, ks=k>>3, kk=k&7
//    word = ((mt*KS+ks)*32 + (r&7)*4 + (kk&3))*4 + (kk>>2)*2 + (r>>3)
//    -> per-fragment load = one LDS.128 at ((mt*KS+ks)*32+lane)*4 (conflict-free)
//  B element (k local, n local):
//    ks=k>>3, kk=k&7, nt=n>>3, g=n&7
//    word = (((nt*KS+ks)*4 + (kk&3))*8 + g)*2 + (kk>>2)
//    -> per-fragment load = one LDS.64 (conflict-free: 16*tig+2*g covers 0..62)

// ---------------------------------------------------------------------------
// GCN GEMM on TF32 tensor cores with 3xTF32 (hi/lo) correction ~ fp32 accuracy.
//   hprime[m,n] = (A[m,:] @ W[:,n]) * inv[m];  agg[m,n] = hprime[m,n]
// BM=128, BN=128, BK=16, K=256, 8 warps (2x4), warp tile 64x32.
// ---------------------------------------------------------------------------
__global__ __launch_bounds__(256, 1) void gcn_gemm_tc_kernel(
    const float* __restrict__ A, const float* __restrict__ B,
    const float* __restrict__ inv,
    float* __restrict__ hprime, float* __restrict__ agg, int M)
{
    __shared__ uint32_t AsH[2048], AsL[2048];   // [8mt][2ks][32lane][4slot]
    __shared__ uint32_t BsH[2048], BsL[2048];   // [16nt][2ks][4tig][8g][2h]

    const int tid  = threadIdx.x;
    const int lane = tid & 31;
    const int warp = tid >> 5;
    const int g    = lane >> 2;
    const int tig  = lane & 3;
    const int wm   = warp & 1;
    const int wn   = warp >> 1;
    const int brow = blockIdx.x * 128;
    const int bcol = blockIdx.y * 128;

    const int ar  = tid >> 1;           // A loader row 0..127
    const int akb = (tid & 1) * 8;      // A loader k-base 0/8
    const int br  = tid >> 4;           // B loader k-row 0..15
    const int bnb = (tid & 15) * 8;     // B loader n-base

    float acc[4][4][4];
    #pragma unroll
    for (int i = 0; i < 4; ++i)
        #pragma unroll
        for (int j = 0; j < 4; ++j)
            #pragma unroll
            for (int c = 0; c < 4; ++c) acc[i][j][c] = 0.f;

    float4 rA[2], rB[2];

    auto loadT = [&](int k0) {
        int grow = brow + ar;
        if (grow < M) {
            const float* ap = A + (size_t)grow * 256 + k0 + akb;
            rA[0] = *(const float4*)ap;
            rA[1] = *(const float4*)(ap + 4);
        } else {
            rA[0] = rA[1] = make_float4(0.f, 0.f, 0.f, 0.f);
        }
        const float* bp = B + (size_t)(k0 + br) * 256 + bcol + bnb;
        rB[0] = *(const float4*)bp;
        rB[1] = *(const float4*)(bp + 4);
    };

    auto storeT = [&]() {
        float av[8] = {rA[0].x, rA[0].y, rA[0].z, rA[0].w,
                       rA[1].x, rA[1].y, rA[1].z, rA[1].w};
        int mt = ar >> 4, r = ar & 15;
        #pragma unroll
        for (int o = 0; o < 8; ++o) {
            int k = akb + o, ks = k >> 3, kk = k & 7;
            int w = ((mt * 2 + ks) * 32 + (r & 7) * 4 + (kk & 3)) * 4
                    + (kk >> 2) * 2 + (r >> 3);
            uint32_t hi = f2tf(av[o]);
            AsH[w] = hi;
            AsL[w] = f2tf(av[o] - __uint_as_float(hi));
        }
        float bv[8] = {rB[0].x, rB[0].y, rB[0].z, rB[0].w,
                       rB[1].x, rB[1].y, rB[1].z, rB[1].w};
        int ks = br >> 3, kk = br & 7, t4 = kk & 3, h = kk >> 2;
        #pragma unroll
        for (int o = 0; o < 8; ++o) {
            int n = bnb + o, nt = n >> 3, g2 = n & 7;
            int w = (((nt * 2 + ks) * 4 + t4) * 8 + g2) * 2 + h;
            uint32_t hi = f2tf(bv[o]);
            BsH[w] = hi;
            BsL[w] = f2tf(bv[o] - __uint_as_float(hi));
        }
    };

    loadT(0);
    storeT();
    __syncthreads();

    for (int k0 = 0; k0 < 256; k0 += 16) {
        bool more = (k0 + 16) < 256;
        if (more) loadT(k0 + 16);

        #pragma unroll
        for (int ks = 0; ks < 2; ++ks) {
            uint32_t afH[4][4], afL[4][4], bfH[4][2], bfL[4][2];
            #pragma unroll
            for (int i = 0; i < 4; ++i) {
                int base = (((wm * 4 + i) * 2 + ks) * 32 + lane) * 4;
                uint4 h4 = *(const uint4*)&AsH[base];
                afH[i][0] = h4.x; afH[i][1] = h4.y; afH[i][2] = h4.z; afH[i][3] = h4.w;
                uint4 l4 = *(const uint4*)&AsL[base];
                afL[i][0] = l4.x; afL[i][1] = l4.y; afL[i][2] = l4.z; afL[i][3] = l4.w;
            }
            #pragma unroll
            for (int jn = 0; jn < 4; ++jn) {
                int base = ((((wn * 4 + jn) * 2 + ks) * 4 + tig) * 8 + g) * 2;
                uint2 h2 = *(const uint2*)&BsH[base];
                bfH[jn][0] = h2.x; bfH[jn][1] = h2.y;
                uint2 l2 = *(const uint2*)&BsL[base];
                bfL[jn][0] = l2.x; bfL[jn][1] = l2.y;
            }
            #pragma unroll
            for (int i = 0; i < 4; ++i)
                #pragma unroll
                for (int jn = 0; jn < 4; ++jn) {
                    mma_tf32(acc[i][jn], afH[i], bfH[jn]);
                    mma_tf32(acc[i][jn], afH[i], bfL[jn]);
                    mma_tf32(acc[i][jn], afL[i], bfH[jn]);
                }
        }
        __syncthreads();
        if (more) { storeT(); __syncthreads(); }
    }

    // epilogue: h' = acc * inv[row]; agg = h'
    #pragma unroll
    for (int i = 0; i < 4; ++i) {
        int r0 = brow + wm * 64 + i * 16 + g;
        int r1 = r0 + 8;
        float iv0 = (r0 < M) ? inv[r0] : 0.f;
        float iv1 = (r1 < M) ? inv[r1] : 0.f;
        #pragma unroll
        for (int jn = 0; jn < 4; ++jn) {
            int c = bcol + wn * 32 + jn * 8 + tig * 2;
            if (r0 < M) {
                float2 o = make_float2(acc[i][jn][0] * iv0, acc[i][jn][1] * iv0);
                *(float2*)(hprime + (size_t)r0 * 256 + c) = o;
                *(float2*)(agg    + (size_t)r0 * 256 + c) = o;
            }
            if (r1 < M) {
                float2 o = make_float2(acc[i][jn][2] * iv1, acc[i][jn][3] * iv1);
                *(float2*)(hprime + (size_t)r1 * 256 + c) = o;
                *(float2*)(agg    + (size_t)r1 * 256 + c) = o;
            }
        }
    }
}

// ---------------------------------------------------------------------------
// Edge scatter: agg[dst,:] += hprime[src,:]   (pure vectorized reductions)
// ---------------------------------------------------------------------------
__global__ void scatter_kernel(const float* __restrict__ hp,
                               const int* __restrict__ src,
                               const int* __restrict__ dst,
                               float* __restrict__ agg, int e)
{
    int warp = (blockIdx.x * blockDim.x + threadIdx.x) >> 5;
    int lane = threadIdx.x & 31;
    if (warp >= e) return;
    int s = __ldg(&src[warp]);
    int d = __ldg(&dst[warp]);
    const float4* hpp = (const float4*)(hp + (size_t)s * 256);
    float* ap = agg + (size_t)d * 256;
    #pragma unroll
    for (int it = 0; it < 2; ++it) {
        int idx = lane + it * 32;
        float4 v = hpp[idx];
        asm volatile("red.global.add.v4.f32 [%0], {%1, %2, %3, %4};"
                     :: "l"(ap + (size_t)idx * 4),
                        "f"(v.x), "f"(v.y), "f"(v.z), "f"(v.w)
                     : "memory");
    }
}

// ---------------------------------------------------------------------------
// Epilogue: feat = agg * inv[row] + b, optional relu  (float4 granularity)
// ---------------------------------------------------------------------------
template <bool RELU>
__global__ void epilogue_kernel(const float* __restrict__ agg,
                                const float* __restrict__ inv,
                                const float* __restrict__ b,
                                float* __restrict__ feat, int total4)
{
    int t = blockIdx.x * blockDim.x + threadIdx.x;
    if (t >= total4) return;
    int row = t >> 6;
    int c4  = t & 63;
    float iv = inv[row];
    float4 v  = ((const float4*)agg)[t];
    float4 bb = ((const float4*)b)[c4];
    v.x = v.x * iv + bb.x; v.y = v.y * iv + bb.y;
    v.z = v.z * iv + bb.z; v.w = v.w * iv + bb.w;
    if (RELU) {
        v.x = fmaxf(v.x, 0.f); v.y = fmaxf(v.y, 0.f);
        v.z = fmaxf(v.z, 0.f); v.w = fmaxf(v.w, 0.f);
    }
    ((float4*)feat)[t] = v;
}

// ---------------------------------------------------------------------------
// Context GEMM on TF32 tensor cores (single pass), fused final product:
//   out[i,c] = feat2[i,c] * ( sum_{j<len[i]} feat2[label[i,j],:] @ Wr[j*256:, c]
//                             + rb[c] )
// BM=128, BN=128, BK=32, fragment-layout smem, per-block K skipping.
// ---------------------------------------------------------------------------
__global__ __launch_bounds__(256, 1) void ctx_gemm_tc_kernel(
    const float* __restrict__ feat,
    const int* __restrict__ label,     // [M, 8]
    const int* __restrict__ clen,      // [M]
    const float* __restrict__ Wr,      // [2048, 256]
    const float* __restrict__ rb,      // [256]
    float* __restrict__ out, int M)
{
    __shared__ uint32_t As[4096];       // [8mt][4ks][32lane][4slot]
    __shared__ uint32_t Bs[4096];       // [16nt][4ks][4tig][8g][2h]
    __shared__ int s_label[128][MAXCTX];
    __shared__ int s_len[128];
    __shared__ int s_maxlen;

    const int brow = blockIdx.x * 128;
    const int bcol = blockIdx.y * 128;
    const int tid  = threadIdx.x;
    const int lane = tid & 31;
    const int warp = tid >> 5;
    const int g    = lane >> 2;
    const int tig  = lane & 3;
    const int wm   = warp & 1;
    const int wn   = warp >> 1;

    // --- stage per-row metadata ---
    if (tid < 128) {
        int gr = brow + tid;
        s_len[tid] = (gr < M) ? clen[gr] : 0;
    }
    for (int i = tid; i < 128 * MAXCTX; i += 256) {
        int r = i >> 3, j = i & 7;
        int gr = brow + r;
        s_label[r][j] = (gr < M) ? label[(size_t)gr * MAXCTX + j] : 0;
    }
    __syncthreads();
    if (warp == 0) {
        int v = max(max(s_len[lane], s_len[lane + 32]),
                    max(s_len[lane + 64], s_len[lane + 96]));
        #pragma unroll
        for (int o = 16; o; o >>= 1) v = max(v, __shfl_xor_sync(0xffffffffu, v, o));
        if (lane == 0) s_maxlen = v;
    }
    __syncthreads();
    const int K_eff = s_maxlen * 256;

    float acc[4][4][4];
    #pragma unroll
    for (int i = 0; i < 4; ++i)
        #pragma unroll
        for (int j = 0; j < 4; ++j)
            #pragma unroll
            for (int c = 0; c < 4; ++c) acc[i][j][c] = 0.f;

    // loader indices
    const int lm  = tid >> 1;          // A row 0..127
    const int lkb = (tid & 1) * 16;    // A k-base 0 / 16
    const int bkk = tid & 31;          // B k-row 0..31
    const int bnb = (tid >> 5) * 16;   // B n-base

    float4 rA[4], rB[4];

    auto loadTiles = [&](int k0) {
        const int j   = k0 >> 8;            // context slot
        const int kc0 = (k0 & 255) + lkb;
        const int L   = s_len[lm];
        const float* abase = feat + (size_t)s_label[lm][j] * HDIM + kc0;
        #pragma unroll
        for (int it = 0; it < 4; ++it) {
            float4 v = make_float4(0.f, 0.f, 0.f, 0.f);
            if (j < L) v = *(const float4*)(abase + it * 4);
            rA[it] = v;
        }
        const float* bbase = Wr + (size_t)(k0 + bkk) * HDIM + bcol + bnb;
        #pragma unroll
        for (int it = 0; it < 4; ++it)
            rB[it] = *(const float4*)(bbase + it * 4);
    };

    auto storeTiles = [&]() {
        float av[16] = {rA[0].x, rA[0].y, rA[0].z, rA[0].w,
                        rA[1].x, rA[1].y, rA[1].z, rA[1].w,
                        rA[2].x, rA[2].y, rA[2].z, rA[2].w,
                        rA[3].x, rA[3].y, rA[3].z, rA[3].w};
        int mt = lm >> 4, r = lm & 15;
        #pragma unroll
        for (int o = 0; o < 16; ++o) {
            int k = lkb + o, ks = k >> 3, kk = k & 7;
            int w = ((mt * 4 + ks) * 32 + (r & 7) * 4 + (kk & 3)) * 4
                    + (kk >> 2) * 2 + (r >> 3);
            As[w] = f2tf(av[o]);
        }
        float bv[16] = {rB[0].x, rB[0].y, rB[0].z, rB[0].w,
                        rB[1].x, rB[1].y, rB[1].z, rB[1].w,
                        rB[2].x, rB[2].y, rB[2].z, rB[2].w,
                        rB[3].x, rB[3].y, rB[3].z, rB[3].w};
        int ks = bkk >> 3, kk = bkk & 7, t4 = kk & 3, h = kk >> 2;
        #pragma unroll
        for (int o = 0; o < 16; ++o) {
            int n = bnb + o, nt = n >> 3, g2 = n & 7;
            int w = (((nt * 4 + ks) * 4 + t4) * 8 + g2) * 2 + h;
            Bs[w] = f2tf(bv[o]);
        }
    };

    if (K_eff > 0) {
        loadTiles(0);
        storeTiles();
        __syncthreads();

        for (int k0 = 0; k0 < K_eff; k0 += 32) {
            bool more = (k0 + 32) < K_eff;
            if (more) loadTiles(k0 + 32);

            #pragma unroll
            for (int ks = 0; ks < 4; ++ks) {
                uint32_t af[4][4], bf[4][2];
                #pragma unroll
                for (int i = 0; i < 4; ++i) {
                    int base = (((wm * 4 + i) * 4 + ks) * 32 + lane) * 4;
                    uint4 a4 = *(const uint4*)&As[base];
                    af[i][0] = a4.x; af[i][1] = a4.y; af[i][2] = a4.z; af[i][3] = a4.w;
                }
                #pragma unroll
                for (int jn = 0; jn < 4; ++jn) {
                    int base = ((((wn * 4 + jn) * 4 + ks) * 4 + tig) * 8 + g) * 2;
                    uint2 b2 = *(const uint2*)&Bs[base];
                    bf[jn][0] = b2.x; bf[jn][1] = b2.y;
                }
                #pragma unroll
                for (int i = 0; i < 4; ++i)
                    #pragma unroll
                    for (int jn = 0; jn < 4; ++jn)
                        mma_tf32(acc[i][jn], af[i], bf[jn]);
            }
            __syncthreads();
            if (more) { storeTiles(); __syncthreads(); }
        }
    }

    // fused epilogue: out = feat2 * (acc + rb)
    #pragma unroll
    for (int i = 0; i < 4; ++i) {
        int r0 = brow + wm * 64 + i * 16 + g;
        int r1 = r0 + 8;
        #pragma unroll
        for (int jn = 0; jn < 4; ++jn) {
            int c = bcol + wn * 32 + jn * 8 + tig * 2;
            float2 bv = *(const float2*)(rb + c);
            if (r0 < M) {
                float2 fv = *(const float2*)(feat + (size_t)r0 * HDIM + c);
                float2 o;
                o.x = (acc[i][jn][0] + bv.x) * fv.x;
                o.y = (acc[i][jn][1] + bv.y) * fv.y;
                *(float2*)(out + (size_t)r0 * HDIM + c) = o;
            }
            if (r1 < M) {
                float2 fv = *(const float2*)(feat + (size_t)r1 * HDIM + c);
                float2 o;
                o.x = (acc[i][jn][2] + bv.x) * fv.x;
                o.y = (acc[i][jn][3] + bv.y) * fv.y;
                *(float2*)(out + (size_t)r1 * HDIM + c) = o;
            }
        }
    }
}

// ---------------------------------------------------------------------------
// Launch
// ---------------------------------------------------------------------------
extern "C" void kernel_launch(void* const* d_in, const int* in_sizes, int n_in,
                              void* d_out, int out_size)
{
    const float* x     = (const float*)d_in[0];
    const int*   ei    = (const int*)  d_in[1];   // [2, E]: src row then dst row
    const int*   label = (const int*)  d_in[2];
    const int*   clen  = (const int*)  d_in[3];
    const float* gW    = (const float*)d_in[4];
    const float* gb    = (const float*)d_in[5];
    const float* rW    = (const float*)d_in[6];
    const float* rb    = (const float*)d_in[7];
    float*       out   = (float*)d_out;

    const int N = in_sizes[3];
    const int E = in_sizes[1] / 2;
    const int* src = ei;
    const int* dst = ei + E;

    float *hp, *agg, *feat, *inv;
    cudaGetSymbolAddress((void**)&hp,   g_h);
    cudaGetSymbolAddress((void**)&agg,  g_agg);
    cudaGetSymbolAddress((void**)&feat, g_feat);
    cudaGetSymbolAddress((void**)&inv,  g_inv);

    const int total4 = N * (HDIM / 4);
    const int TPB = 256;
    dim3 gemm_grid((N + 127) / 128, 2);

    // --- normalization ---
    deg_init_kernel<<<(N + TPB - 1) / TPB, TPB>>>(inv, N);
    deg_count_kernel<<<(E + TPB - 1) / TPB, TPB>>>(dst, inv, E);
    inv_sqrt_kernel<<<(N + TPB - 1) / TPB, TPB>>>(inv, N);

    // --- GCN layer 1: feat1 = relu(inv * (scatter(h') ) + b),  h' = (x@W)*inv ---
    gcn_gemm_tc_kernel<<<gemm_grid, TPB>>>(x, gW, inv, hp, agg, N);
    scatter_kernel<<<(E * 32 + TPB - 1) / TPB, TPB>>>(hp, src, dst, agg, E);
    epilogue_kernel<true><<<(total4 + TPB - 1) / TPB, TPB>>>(agg, inv, gb, feat, total4);

    // --- GCN layer 2 ---
    gcn_gemm_tc_kernel<<<gemm_grid, TPB>>>(feat, gW, inv, hp, agg, N);
    scatter_kernel<<<(E * 32 + TPB - 1) / TPB, TPB>>>(hp, src, dst, agg, E);
    epilogue_kernel<false><<<(total4 + TPB - 1) / TPB, TPB>>>(agg, inv, gb, feat, total4);

    // --- context gather-GEMM on TF32 tensor cores, fused final product ---
    ctx_gemm_tc_kernel<<<gemm_grid, TPB>>>(feat, label, clen, rW, rb, out, N);
}

// round 9
// speedup vs baseline: 1.0000x; 1.0000x over previous
#include <cuda_runtime.h>
#include <cstdint>

#define N_MAX   50000
#define HDIM    256
#define E_MAX   800000
#define MAXCTX  8

// ---------------------------------------------------------------------------
// Scratch (device globals -- no allocation allowed in kernel_launch)
// ---------------------------------------------------------------------------
__device__ float g_h[N_MAX * HDIM];     // h' = (A @ W) * inv[row]
__device__ float g_agg[N_MAX * HDIM];   // scatter accumulator
__device__ float g_feat[N_MAX * HDIM];  // layer output (feat1 then feat2)
__device__ float g_inv[N_MAX];          // deg, then rsqrt(deg)

// ---------------------------------------------------------------------------
// Degree / normalization
// ---------------------------------------------------------------------------
__global__ void deg_init_kernel(float* deg, int n) {
    int i = blockIdx.x * blockDim.x + threadIdx.x;
    if (i < n) deg[i] = 1.0f;  // self loop
}

__global__ void deg_count_kernel(const int* __restrict__ dst, float* deg, int e) {
    int i = blockIdx.x * blockDim.x + threadIdx.x;
    if (i < e) atomicAdd(&deg[dst[i]], 1.0f);
}

__global__ void inv_sqrt_kernel(float* deg, int n) {
    int i = blockIdx.x * blockDim.x + threadIdx.x;
    if (i < n) deg[i] = rsqrtf(deg[i]);   // deg >= 1 always
}

// ---------------------------------------------------------------------------
// TF32 helpers
// ---------------------------------------------------------------------------
__device__ __forceinline__ uint32_t f2tf(float x) {
    uint32_t r;
    asm("cvt.rna.tf32.f32 %0, %1;" : "=r"(r) : "f"(x));
    return r;
}

__device__ __forceinline__ void mma_tf32(float d[4], const uint32_t a[4],
                                         const uint32_t b[2]) {
    asm volatile(
        "mma.sync.aligned.m16n8k8.row.col.f32.tf32.tf32.f32 "
        "{%0,%1,%2,%3}, {%4,%5,%6,%7}, {%8,%9}, {%0,%1,%2,%3};"
        : "+f"(d[0]), "+f"(d[1]), "+f"(d[2]), "+f"(d[3])
        : "r"(a[0]), "r"(a[1]), "r"(a[2]), "r"(a[3]),
          "r"(b[0]), "r"(b[1]));
}

// Fragment-layout smem addressing (m16n8k8):
//  A element (m local, k local) for BK with KS k-steps:
//    mt=m>>4, r=m&15, ks=k>>3, kk=k&7
//    word = ((mt*KS+ks)*32 + (r&7)*4 + (kk&3))*4 + (kk>>2)*2 + (r>>3)
//    -> per-fragment load = one LDS.128 at ((mt*KS+ks)*32+lane)*4 (conflict-free)
//  B element (k local, n local):
//    ks=k>>3, kk=k&7, nt=n>>3, g=n&7
//    word = (((nt*KS+ks)*4 + (kk&3))*8 + g)*2 + (kk>>2)
//    -> per-fragment load = one LDS.64 (conflict-free: 16*tig+2*g covers 0..62)

// ---------------------------------------------------------------------------
// GCN GEMM on TF32 tensor cores with 3xTF32 (hi/lo) correction ~ fp32 accuracy.
//   hprime[m,n] = (A[m,:] @ W[:,n]) * inv[m];  agg[m,n] = hprime[m,n]
// BM=128, BN=128, BK=16, K=256, 8 warps (2x4), warp tile 64x32.
// ---------------------------------------------------------------------------
__global__ __launch_bounds__(256, 1) void gcn_gemm_tc_kernel(
    const float* __restrict__ A, const float* __restrict__ B,
    const float* __restrict__ inv,
    float* __restrict__ hprime, float* __restrict__ agg, int M)
{
    __shared__ uint32_t AsH[2048], AsL[2048];   // [8mt][2ks][32lane][4slot]
    __shared__ uint32_t BsH[2048], BsL[2048];   // [16nt][2ks][4tig][8g][2h]

    const int tid  = threadIdx.x;
    const int lane = tid & 31;
    const int warp = tid >> 5;
    const int g    = lane >> 2;
    const int tig  = lane & 3;
    const int wm   = warp & 1;
    const int wn   = warp >> 1;
    const int brow = blockIdx.x * 128;
    const int bcol = blockIdx.y * 128;

    const int ar  = tid >> 1;           // A loader row 0..127
    const int akb = (tid & 1) * 8;      // A loader k-base 0/8
    const int br  = tid >> 4;           // B loader k-row 0..15
    const int bnb = (tid & 15) * 8;     // B loader n-base

    float acc[4][4][4];
    #pragma unroll
    for (int i = 0; i < 4; ++i)
        #pragma unroll
        for (int j = 0; j < 4; ++j)
            #pragma unroll
            for (int c = 0; c < 4; ++c) acc[i][j][c] = 0.f;

    float4 rA[2], rB[2];

    auto loadT = [&](int k0) {
        int grow = brow + ar;
        if (grow < M) {
            const float* ap = A + (size_t)grow * 256 + k0 + akb;
            rA[0] = *(const float4*)ap;
            rA[1] = *(const float4*)(ap + 4);
        } else {
            rA[0] = rA[1] = make_float4(0.f, 0.f, 0.f, 0.f);
        }
        const float* bp = B + (size_t)(k0 + br) * 256 + bcol + bnb;
        rB[0] = *(const float4*)bp;
        rB[1] = *(const float4*)(bp + 4);
    };

    auto storeT = [&]() {
        float av[8] = {rA[0].x, rA[0].y, rA[0].z, rA[0].w,
                       rA[1].x, rA[1].y, rA[1].z, rA[1].w};
        int mt = ar >> 4, r = ar & 15;
        #pragma unroll
        for (int o = 0; o < 8; ++o) {
            int k = akb + o, ks = k >> 3, kk = k & 7;
            int w = ((mt * 2 + ks) * 32 + (r & 7) * 4 + (kk & 3)) * 4
                    + (kk >> 2) * 2 + (r >> 3);
            uint32_t hi = f2tf(av[o]);
            AsH[w] = hi;
            AsL[w] = f2tf(av[o] - __uint_as_float(hi));
        }
        float bv[8] = {rB[0].x, rB[0].y, rB[0].z, rB[0].w,
                       rB[1].x, rB[1].y, rB[1].z, rB[1].w};
        int ks = br >> 3, kk = br & 7, t4 = kk & 3, h = kk >> 2;
        #pragma unroll
        for (int o = 0; o < 8; ++o) {
            int n = bnb + o, nt = n >> 3, g2 = n & 7;
            int w = (((nt * 2 + ks) * 4 + t4) * 8 + g2) * 2 + h;
            uint32_t hi = f2tf(bv[o]);
            BsH[w] = hi;
            BsL[w] = f2tf(bv[o] - __uint_as_float(hi));
        }
    };

    loadT(0);
    storeT();
    __syncthreads();

    for (int k0 = 0; k0 < 256; k0 += 16) {
        bool more = (k0 + 16) < 256;
        if (more) loadT(k0 + 16);

        #pragma unroll
        for (int ks = 0; ks < 2; ++ks) {
            uint32_t afH[4][4], afL[4][4], bfH[4][2], bfL[4][2];
            #pragma unroll
            for (int i = 0; i < 4; ++i) {
                int base = (((wm * 4 + i) * 2 + ks) * 32 + lane) * 4;
                uint4 h4 = *(const uint4*)&AsH[base];
                afH[i][0] = h4.x; afH[i][1] = h4.y; afH[i][2] = h4.z; afH[i][3] = h4.w;
                uint4 l4 = *(const uint4*)&AsL[base];
                afL[i][0] = l4.x; afL[i][1] = l4.y; afL[i][2] = l4.z; afL[i][3] = l4.w;
            }
            #pragma unroll
            for (int jn = 0; jn < 4; ++jn) {
                int base = ((((wn * 4 + jn) * 2 + ks) * 4 + tig) * 8 + g) * 2;
                uint2 h2 = *(const uint2*)&BsH[base];
                bfH[jn][0] = h2.x; bfH[jn][1] = h2.y;
                uint2 l2 = *(const uint2*)&BsL[base];
                bfL[jn][0] = l2.x; bfL[jn][1] = l2.y;
            }
            #pragma unroll
            for (int i = 0; i < 4; ++i)
                #pragma unroll
                for (int jn = 0; jn < 4; ++jn) {
                    mma_tf32(acc[i][jn], afH[i], bfH[jn]);
                    mma_tf32(acc[i][jn], afH[i], bfL[jn]);
                    mma_tf32(acc[i][jn], afL[i], bfH[jn]);
                }
        }
        __syncthreads();
        if (more) { storeT(); __syncthreads(); }
    }

    // epilogue: h' = acc * inv[row]; agg = h'
    #pragma unroll
    for (int i = 0; i < 4; ++i) {
        int r0 = brow + wm * 64 + i * 16 + g;
        int r1 = r0 + 8;
        float iv0 = (r0 < M) ? inv[r0] : 0.f;
        float iv1 = (r1 < M) ? inv[r1] : 0.f;
        #pragma unroll
        for (int jn = 0; jn < 4; ++jn) {
            int c = bcol + wn * 32 + jn * 8 + tig * 2;
            if (r0 < M) {
                float2 o = make_float2(acc[i][jn][0] * iv0, acc[i][jn][1] * iv0);
                *(float2*)(hprime + (size_t)r0 * 256 + c) = o;
                *(float2*)(agg    + (size_t)r0 * 256 + c) = o;
            }
            if (r1 < M) {
                float2 o = make_float2(acc[i][jn][2] * iv1, acc[i][jn][3] * iv1);
                *(float2*)(hprime + (size_t)r1 * 256 + c) = o;
                *(float2*)(agg    + (size_t)r1 * 256 + c) = o;
            }
        }
    }
}

// ---------------------------------------------------------------------------
// Edge scatter: agg[dst,:] += hprime[src,:]   (pure vectorized reductions)
// ---------------------------------------------------------------------------
__global__ void scatter_kernel(const float* __restrict__ hp,
                               const int* __restrict__ src,
                               const int* __restrict__ dst,
                               float* __restrict__ agg, int e)
{
    int warp = (blockIdx.x * blockDim.x + threadIdx.x) >> 5;
    int lane = threadIdx.x & 31;
    if (warp >= e) return;
    int s = __ldg(&src[warp]);
    int d = __ldg(&dst[warp]);
    const float4* hpp = (const float4*)(hp + (size_t)s * 256);
    float* ap = agg + (size_t)d * 256;
    #pragma unroll
    for (int it = 0; it < 2; ++it) {
        int idx = lane + it * 32;
        float4 v = hpp[idx];
        asm volatile("red.global.add.v4.f32 [%0], {%1, %2, %3, %4};"
                     :: "l"(ap + (size_t)idx * 4),
                        "f"(v.x), "f"(v.y), "f"(v.z), "f"(v.w)
                     : "memory");
    }
}

// ---------------------------------------------------------------------------
// Epilogue: feat = agg * inv[row] + b, optional relu  (float4 granularity)
// ---------------------------------------------------------------------------
template <bool RELU>
__global__ void epilogue_kernel(const float* __restrict__ agg,
                                const float* __restrict__ inv,
                                const float* __restrict__ b,
                                float* __restrict__ feat, int total4)
{
    int t = blockIdx.x * blockDim.x + threadIdx.x;
    if (t >= total4) return;
    int row = t >> 6;
    int c4  = t & 63;
    float iv = inv[row];
    float4 v  = ((const float4*)agg)[t];
    float4 bb = ((const float4*)b)[c4];
    v.x = v.x * iv + bb.x; v.y = v.y * iv + bb.y;
    v.z = v.z * iv + bb.z; v.w = v.w * iv + bb.w;
    if (RELU) {
        v.x = fmaxf(v.x, 0.f); v.y = fmaxf(v.y, 0.f);
        v.z = fmaxf(v.z, 0.f); v.w = fmaxf(v.w, 0.f);
    }
    ((float4*)feat)[t] = v;
}

// ---------------------------------------------------------------------------
// Context GEMM on TF32 tensor cores (single pass), fused final product:
//   out[i,c] = feat2[i,c] * ( sum_{j<len[i]} feat2[label[i,j],:] @ Wr[j*256:, c]
//                             + rb[c] )
// BM=128, BN=128, BK=32, fragment-layout smem, per-block K skipping.
// ---------------------------------------------------------------------------
__global__ __launch_bounds__(256, 1) void ctx_gemm_tc_kernel(
    const float* __restrict__ feat,
    const int* __restrict__ label,     // [M, 8]
    const int* __restrict__ clen,      // [M]
    const float* __restrict__ Wr,      // [2048, 256]
    const float* __restrict__ rb,      // [256]
    float* __restrict__ out, int M)
{
    __shared__ uint32_t As[4096];       // [8mt][4ks][32lane][4slot]
    __shared__ uint32_t Bs[4096];       // [16nt][4ks][4tig][8g][2h]
    __shared__ int s_label[128][MAXCTX];
    __shared__ int s_len[128];
    __shared__ int s_maxlen;

    const int brow = blockIdx.x * 128;
    const int bcol = blockIdx.y * 128;
    const int tid  = threadIdx.x;
    const int lane = tid & 31;
    const int warp = tid >> 5;
    const int g    = lane >> 2;
    const int tig  = lane & 3;
    const int wm   = warp & 1;
    const int wn   = warp >> 1;

    // --- stage per-row metadata ---
    if (tid < 128) {
        int gr = brow + tid;
        s_len[tid] = (gr < M) ? clen[gr] : 0;
    }
    for (int i = tid; i < 128 * MAXCTX; i += 256) {
        int r = i >> 3, j = i & 7;
        int gr = brow + r;
        s_label[r][j] = (gr < M) ? label[(size_t)gr * MAXCTX + j] : 0;
    }
    __syncthreads();
    if (warp == 0) {
        int v = max(max(s_len[lane], s_len[lane + 32]),
                    max(s_len[lane + 64], s_len[lane + 96]));
        #pragma unroll
        for (int o = 16; o; o >>= 1) v = max(v, __shfl_xor_sync(0xffffffffu, v, o));
        if (lane == 0) s_maxlen = v;
    }
    __syncthreads();
    const int K_eff = s_maxlen * 256;

    float acc[4][4][4];
    #pragma unroll
    for (int i = 0; i < 4; ++i)
        #pragma unroll
        for (int j = 0; j < 4; ++j)
            #pragma unroll
            for (int c = 0; c < 4; ++c) acc[i][j][c] = 0.f;

    // loader indices
    const int lm  = tid >> 1;          // A row 0..127
    const int lkb = (tid & 1) * 16;    // A k-base 0 / 16
    const int bkk = tid & 31;          // B k-row 0..31
    const int bnb = (tid >> 5) * 16;   // B n-base

    float4 rA[4], rB[4];

    auto loadTiles = [&](int k0) {
        const int j   = k0 >> 8;            // context slot
        const int kc0 = (k0 & 255) + lkb;
        const int L   = s_len[lm];
        const float* abase = feat + (size_t)s_label[lm][j] * HDIM + kc0;
        #pragma unroll
        for (int it = 0; it < 4; ++it) {
            float4 v = make_float4(0.f, 0.f, 0.f, 0.f);
            if (j < L) v = *(const float4*)(abase + it * 4);
            rA[it] = v;
        }
        const float* bbase = Wr + (size_t)(k0 + bkk) * HDIM + bcol + bnb;
        #pragma unroll
        for (int it = 0; it < 4; ++it)
            rB[it] = *(const float4*)(bbase + it * 4);
    };

    auto storeTiles = [&]() {
        float av[16] = {rA[0].x, rA[0].y, rA[0].z, rA[0].w,
                        rA[1].x, rA[1].y, rA[1].z, rA[1].w,
                        rA[2].x, rA[2].y, rA[2].z, rA[2].w,
                        rA[3].x, rA[3].y, rA[3].z, rA[3].w};
        int mt = lm >> 4, r = lm & 15;
        #pragma unroll
        for (int o = 0; o < 16; ++o) {
            int k = lkb + o, ks = k >> 3, kk = k & 7;
            int w = ((mt * 4 + ks) * 32 + (r & 7) * 4 + (kk & 3)) * 4
                    + (kk >> 2) * 2 + (r >> 3);
            As[w] = f2tf(av[o]);
        }
        float bv[16] = {rB[0].x, rB[0].y, rB[0].z, rB[0].w,
                        rB[1].x, rB[1].y, rB[1].z, rB[1].w,
                        rB[2].x, rB[2].y, rB[2].z, rB[2].w,
                        rB[3].x, rB[3].y, rB[3].z, rB[3].w};
        int ks = bkk >> 3, kk = bkk & 7, t4 = kk & 3, h = kk >> 2;
        #pragma unroll
        for (int o = 0; o < 16; ++o) {
            int n = bnb + o, nt = n >> 3, g2 = n & 7;
            int w = (((nt * 4 + ks) * 4 + t4) * 8 + g2) * 2 + h;
            Bs[w] = f2tf(bv[o]);
        }
    };

    if (K_eff > 0) {
        loadTiles(0);
        storeTiles();
        __syncthreads();

        for (int k0 = 0; k0 < K_eff; k0 += 32) {
            bool more = (k0 + 32) < K_eff;
            if (more) loadTiles(k0 + 32);

            #pragma unroll
            for (int ks = 0; ks < 4; ++ks) {
                uint32_t af[4][4], bf[4][2];
                #pragma unroll
                for (int i = 0; i < 4; ++i) {
                    int base = (((wm * 4 + i) * 4 + ks) * 32 + lane) * 4;
                    uint4 a4 = *(const uint4*)&As[base];
                    af[i][0] = a4.x; af[i][1] = a4.y; af[i][2] = a4.z; af[i][3] = a4.w;
                }
                #pragma unroll
                for (int jn = 0; jn < 4; ++jn) {
                    int base = ((((wn * 4 + jn) * 4 + ks) * 4 + tig) * 8 + g) * 2;
                    uint2 b2 = *(const uint2*)&Bs[base];
                    bf[jn][0] = b2.x; bf[jn][1] = b2.y;
                }
                #pragma unroll
                for (int i = 0; i < 4; ++i)
                    #pragma unroll
                    for (int jn = 0; jn < 4; ++jn)
                        mma_tf32(acc[i][jn], af[i], bf[jn]);
            }
            __syncthreads();
            if (more) { storeTiles(); __syncthreads(); }
        }
    }

    // fused epilogue: out = feat2 * (acc + rb)
    #pragma unroll
    for (int i = 0; i < 4; ++i) {
        int r0 = brow + wm * 64 + i * 16 + g;
        int r1 = r0 + 8;
        #pragma unroll
        for (int jn = 0; jn < 4; ++jn) {
            int c = bcol + wn * 32 + jn * 8 + tig * 2;
            float2 bv = *(const float2*)(rb + c);
            if (r0 < M) {
                float2 fv = *(const float2*)(feat + (size_t)r0 * HDIM + c);
                float2 o;
                o.x = (acc[i][jn][0] + bv.x) * fv.x;
                o.y = (acc[i][jn][1] + bv.y) * fv.y;
                *(float2*)(out + (size_t)r0 * HDIM + c) = o;
            }
            if (r1 < M) {
                float2 fv = *(const float2*)(feat + (size_t)r1 * HDIM + c);
                float2 o;
                o.x = (acc[i][jn][2] + bv.x) * fv.x;
                o.y = (acc[i][jn][3] + bv.y) * fv.y;
                *(float2*)(out + (size_t)r1 * HDIM + c) = o;
            }
        }
    }
}

// ---------------------------------------------------------------------------
// Launch
// ---------------------------------------------------------------------------
extern "C" void kernel_launch(void* const* d_in, const int* in_sizes, int n_in,
                              void* d_out, int out_size)
{
    const float* x     = (const float*)d_in[0];
    const int*   ei    = (const int*)  d_in[1];   // [2, E]: src row then dst row
    const int*   label = (const int*)  d_in[2];
    const int*   clen  = (const int*)  d_in[3];
    const float* gW    = (const float*)d_in[4];
    const float* gb    = (const float*)d_in[5];
    const float* rW    = (const float*)d_in[6];
    const float* rb    = (const float*)d_in[7];
    float*       out   = (float*)d_out;

    const int N = in_sizes[3];
    const int E = in_sizes[1] / 2;
    const int* src = ei;
    const int* dst = ei + E;

    float *hp, *agg, *feat, *inv;
    cudaGetSymbolAddress((void**)&hp,   g_h);
    cudaGetSymbolAddress((void**)&agg,  g_agg);
    cudaGetSymbolAddress((void**)&feat, g_feat);
    cudaGetSymbolAddress((void**)&inv,  g_inv);

    const int total4 = N * (HDIM / 4);
    const int TPB = 256;
    dim3 gemm_grid((N + 127) / 128, 2);

    // --- normalization ---
    deg_init_kernel<<<(N + TPB - 1) / TPB, TPB>>>(inv, N);
    deg_count_kernel<<<(E + TPB - 1) / TPB, TPB>>>(dst, inv, E);
    inv_sqrt_kernel<<<(N + TPB - 1) / TPB, TPB>>>(inv, N);

    // --- GCN layer 1: feat1 = relu(inv * (scatter(h') ) + b),  h' = (x@W)*inv ---
    gcn_gemm_tc_kernel<<<gemm_grid, TPB>>>(x, gW, inv, hp, agg, N);
    scatter_kernel<<<(E * 32 + TPB - 1) / TPB, TPB>>>(hp, src, dst, agg, E);
    epilogue_kernel<true><<<(total4 + TPB - 1) / TPB, TPB>>>(agg, inv, gb, feat, total4);

    // --- GCN layer 2 ---
    gcn_gemm_tc_kernel<<<gemm_grid, TPB>>>(feat, gW, inv, hp, agg, N);
    scatter_kernel<<<(E * 32 + TPB - 1) / TPB, TPB>>>(hp, src, dst, agg, E);
    epilogue_kernel<false><<<(total4 + TPB - 1) / TPB, TPB>>>(agg, inv, gb, feat, total4);

    // --- context gather-GEMM on TF32 tensor cores, fused final product ---
    ctx_gemm_tc_kernel<<<gemm_grid, TPB>>>(feat, label, clen, rW, rb, out, N);
}

// round 10
// speedup vs baseline: 1.0578x; 1.0578x over previous
#include <cuda_runtime.h>
#include <cstdint>

#define N_MAX   50000
#define HDIM    256
#define E_MAX   800000
#define MAXCTX  8

// ---------------------------------------------------------------------------
// Scratch (device globals -- no allocation allowed in kernel_launch)
// ---------------------------------------------------------------------------
__device__ float g_h[N_MAX * HDIM];     // h' = (A @ W) * inv[row]
__device__ float g_agg[N_MAX * HDIM];   // scatter accumulator
__device__ float g_feat[N_MAX * HDIM];  // layer output (feat1 then feat2)
__device__ float g_inv[N_MAX];          // deg, then rsqrt(deg)
__device__ int   g_bcnt[MAXCTX];        // bucket counts (clen in 0..7)
__device__ int   g_boff[MAXCTX];        // bucket offsets (mutated by scatter)
__device__ int   g_perm[N_MAX];         // rows sorted by context_len

// ---------------------------------------------------------------------------
// Degree / normalization
// ---------------------------------------------------------------------------
__global__ void deg_init_kernel(float* deg, int n) {
    int i = blockIdx.x * blockDim.x + threadIdx.x;
    if (i < n) deg[i] = 1.0f;  // self loop
}

__global__ void deg_count_kernel(const int* __restrict__ dst, float* deg, int e) {
    int i = blockIdx.x * blockDim.x + threadIdx.x;
    if (i < e) atomicAdd(&deg[dst[i]], 1.0f);
}

__global__ void inv_sqrt_kernel(float* deg, int n) {
    int i = blockIdx.x * blockDim.x + threadIdx.x;
    if (i < n) deg[i] = rsqrtf(deg[i]);
}

// ---------------------------------------------------------------------------
// Bucket sort of rows by context_len (8 bins)
// ---------------------------------------------------------------------------
__global__ void bucket_init_kernel() {
    if (threadIdx.x < MAXCTX) g_bcnt[threadIdx.x] = 0;
}
__global__ void bucket_hist_kernel(const int* __restrict__ clen, int n) {
    int i = blockIdx.x * blockDim.x + threadIdx.x;
    if (i < n) atomicAdd(&g_bcnt[clen[i]], 1);
}
__global__ void bucket_scan_kernel() {
    if (threadIdx.x == 0) {
        int acc = 0;
        for (int b = 0; b < MAXCTX; ++b) { g_boff[b] = acc; acc += g_bcnt[b]; }
    }
}
__global__ void bucket_scatter_kernel(const int* __restrict__ clen, int n) {
    int i = blockIdx.x * blockDim.x + threadIdx.x;
    if (i < n) {
        int p = atomicAdd(&g_boff[clen[i]], 1);
        g_perm[p] = i;
    }
}

// ---------------------------------------------------------------------------
// TF32 helpers
// ---------------------------------------------------------------------------
__device__ __forceinline__ uint32_t f2tf(float x) {
    uint32_t r;
    asm("cvt.rna.tf32.f32 %0, %1;" : "=r"(r) : "f"(x));
    return r;
}

__device__ __forceinline__ void mma_tf32(float d[4], const uint32_t a[4],
                                         const uint32_t b[2]) {
    asm volatile(
        "mma.sync.aligned.m16n8k8.row.col.f32.tf32.tf32.f32 "
        "{%0,%1,%2,%3}, {%4,%5,%6,%7}, {%8,%9}, {%0,%1,%2,%3};"
        : "+f"(d[0]), "+f"(d[1]), "+f"(d[2]), "+f"(d[3])
        : "r"(a[0]), "r"(a[1]), "r"(a[2]), "r"(a[3]),
          "r"(b[0]), "r"(b[1]));
}

// Fragment-layout smem addressing (validated in R9), KS = 4 k-steps per BK=32:
//  A word = ((mt*4+ks)*32 + (r&7)*4 + (kk&3))*4 + (kk>>2)*2 + (r>>3)
//    -> fragment load = one conflict-free LDS.128 at ((mt*4+ks)*32+lane)*4
//  B word = (((nt*4+ks)*4 + (kk&3))*8 + g)*2 + (kk>>2)
//    -> fragment load = one conflict-free LDS.64

// ---------------------------------------------------------------------------
// GCN GEMM, 3xTF32 corrected (~fp32 accuracy):
//   hprime = (A @ W) * inv[row];  agg = hprime
// BM=128, BN=64, BK=32, 8 warps (4x2), warp tile 32x32, 2 CTAs/SM target.
// ---------------------------------------------------------------------------
__global__ __launch_bounds__(256, 2) void gcn_gemm_tc_kernel(
    const float* __restrict__ A, const float* __restrict__ B,
    const float* __restrict__ inv,
    float* __restrict__ hprime, float* __restrict__ agg, int M)
{
    __shared__ uint32_t AsH[4096], AsL[4096];   // 128m x 32k (hi/lo)
    __shared__ uint32_t BsH[2048], BsL[2048];   // 32k x 64n  (hi/lo)

    const int tid  = threadIdx.x;
    const int lane = tid & 31;
    const int warp = tid >> 5;
    const int g    = lane >> 2;
    const int tig  = lane & 3;
    const int wm   = warp & 3;     // 4 warp rows
    const int wn   = warp >> 2;    // 2 warp cols
    const int brow = blockIdx.x * 128;
    const int bcol = blockIdx.y * 64;

    const int lm  = tid >> 1;          // A row 0..127
    const int lkb = (tid & 1) * 16;    // A k-base 0/16
    const int bkk = tid >> 3;          // B k-row 0..31
    const int bnb = (tid & 7) * 8;     // B n-base 0..56

    float acc[2][4][4];
    #pragma unroll
    for (int i = 0; i < 2; ++i)
        #pragma unroll
        for (int j = 0; j < 4; ++j)
            #pragma unroll
            for (int c = 0; c < 4; ++c) acc[i][j][c] = 0.f;

    float4 rA[4], rB[2];

    auto loadT = [&](int k0) {
        int grow = brow + lm;
        const float* ap = A + (size_t)grow * 256 + k0 + lkb;
        #pragma unroll
        for (int it = 0; it < 4; ++it)
            rA[it] = (grow < M) ? *(const float4*)(ap + it * 4)
                                : make_float4(0.f, 0.f, 0.f, 0.f);
        const float* bp = B + (size_t)(k0 + bkk) * 256 + bcol + bnb;
        rB[0] = *(const float4*)bp;
        rB[1] = *(const float4*)(bp + 4);
    };

    auto storeT = [&]() {
        float av[16] = {rA[0].x, rA[0].y, rA[0].z, rA[0].w,
                        rA[1].x, rA[1].y, rA[1].z, rA[1].w,
                        rA[2].x, rA[2].y, rA[2].z, rA[2].w,
                        rA[3].x, rA[3].y, rA[3].z, rA[3].w};
        int mt = lm >> 4, r = lm & 15;
        #pragma unroll
        for (int o = 0; o < 16; ++o) {
            int k = lkb + o, ks = k >> 3, kk = k & 7;
            int w = ((mt * 4 + ks) * 32 + (r & 7) * 4 + (kk & 3)) * 4
                    + (kk >> 2) * 2 + (r >> 3);
            uint32_t hi = f2tf(av[o]);
            AsH[w] = hi;
            AsL[w] = f2tf(av[o] - __uint_as_float(hi));
        }
        float bv[8] = {rB[0].x, rB[0].y, rB[0].z, rB[0].w,
                       rB[1].x, rB[1].y, rB[1].z, rB[1].w};
        int ks = bkk >> 3, kk = bkk & 7, t4 = kk & 3, h = kk >> 2;
        #pragma unroll
        for (int o = 0; o < 8; ++o) {
            int n = bnb + o, nt = n >> 3, g2 = n & 7;
            int w = (((nt * 4 + ks) * 4 + t4) * 8 + g2) * 2 + h;
            uint32_t hi = f2tf(bv[o]);
            BsH[w] = hi;
            BsL[w] = f2tf(bv[o] - __uint_as_float(hi));
        }
    };

    loadT(0);
    storeT();
    __syncthreads();

    for (int k0 = 0; k0 < 256; k0 += 32) {
        bool more = (k0 + 32) < 256;
        if (more) loadT(k0 + 32);

        #pragma unroll
        for (int ks = 0; ks < 4; ++ks) {
            uint32_t afH[2][4], afL[2][4], bfH[4][2], bfL[4][2];
            #pragma unroll
            for (int i = 0; i < 2; ++i) {
                int base = (((wm * 2 + i) * 4 + ks) * 32 + lane) * 4;
                uint4 h4 = *(const uint4*)&AsH[base];
                afH[i][0] = h4.x; afH[i][1] = h4.y; afH[i][2] = h4.z; afH[i][3] = h4.w;
                uint4 l4 = *(const uint4*)&AsL[base];
                afL[i][0] = l4.x; afL[i][1] = l4.y; afL[i][2] = l4.z; afL[i][3] = l4.w;
            }
            #pragma unroll
            for (int jn = 0; jn < 4; ++jn) {
                int base = ((((wn * 4 + jn) * 4 + ks) * 4 + tig) * 8 + g) * 2;
                uint2 h2 = *(const uint2*)&BsH[base];
                bfH[jn][0] = h2.x; bfH[jn][1] = h2.y;
                uint2 l2 = *(const uint2*)&BsL[base];
                bfL[jn][0] = l2.x; bfL[jn][1] = l2.y;
            }
            #pragma unroll
            for (int i = 0; i < 2; ++i)
                #pragma unroll
                for (int jn = 0; jn < 4; ++jn) {
                    mma_tf32(acc[i][jn], afH[i], bfH[jn]);
                    mma_tf32(acc[i][jn], afH[i], bfL[jn]);
                    mma_tf32(acc[i][jn], afL[i], bfH[jn]);
                }
        }
        __syncthreads();
        if (more) { storeT(); __syncthreads(); }
    }

    // epilogue: h' = acc * inv[row]; agg = h'
    #pragma unroll
    for (int i = 0; i < 2; ++i) {
        int r0 = brow + (wm * 2 + i) * 16 + g;
        int r1 = r0 + 8;
        float iv0 = (r0 < M) ? inv[r0] : 0.f;
        float iv1 = (r1 < M) ? inv[r1] : 0.f;
        #pragma unroll
        for (int jn = 0; jn < 4; ++jn) {
            int c = bcol + (wn * 4 + jn) * 8 + tig * 2;
            if (r0 < M) {
                float2 o = make_float2(acc[i][jn][0] * iv0, acc[i][jn][1] * iv0);
                *(float2*)(hprime + (size_t)r0 * 256 + c) = o;
                *(float2*)(agg    + (size_t)r0 * 256 + c) = o;
            }
            if (r1 < M) {
                float2 o = make_float2(acc[i][jn][2] * iv1, acc[i][jn][3] * iv1);
                *(float2*)(hprime + (size_t)r1 * 256 + c) = o;
                *(float2*)(agg    + (size_t)r1 * 256 + c) = o;
            }
        }
    }
}

// ---------------------------------------------------------------------------
// Edge scatter: agg[dst,:] += hprime[src,:]   (pure vectorized reductions)
// ---------------------------------------------------------------------------
__global__ void scatter_kernel(const float* __restrict__ hp,
                               const int* __restrict__ src,
                               const int* __restrict__ dst,
                               float* __restrict__ agg, int e)
{
    int warp = (blockIdx.x * blockDim.x + threadIdx.x) >> 5;
    int lane = threadIdx.x & 31;
    if (warp >= e) return;
    int s = __ldg(&src[warp]);
    int d = __ldg(&dst[warp]);
    const float4* hpp = (const float4*)(hp + (size_t)s * 256);
    float* ap = agg + (size_t)d * 256;
    #pragma unroll
    for (int it = 0; it < 2; ++it) {
        int idx = lane + it * 32;
        float4 v = hpp[idx];
        asm volatile("red.global.add.v4.f32 [%0], {%1, %2, %3, %4};"
                     :: "l"(ap + (size_t)idx * 4),
                        "f"(v.x), "f"(v.y), "f"(v.z), "f"(v.w)
                     : "memory");
    }
}

// ---------------------------------------------------------------------------
// Epilogue: feat = agg * inv[row] + b, optional relu
// ---------------------------------------------------------------------------
template <bool RELU>
__global__ void epilogue_kernel(const float* __restrict__ agg,
                                const float* __restrict__ inv,
                                const float* __restrict__ b,
                                float* __restrict__ feat, int total4)
{
    int t = blockIdx.x * blockDim.x + threadIdx.x;
    if (t >= total4) return;
    int row = t >> 6;
    int c4  = t & 63;
    float iv = inv[row];
    float4 v  = ((const float4*)agg)[t];
    float4 bb = ((const float4*)b)[c4];
    v.x = v.x * iv + bb.x; v.y = v.y * iv + bb.y;
    v.z = v.z * iv + bb.z; v.w = v.w * iv + bb.w;
    if (RELU) {
        v.x = fmaxf(v.x, 0.f); v.y = fmaxf(v.y, 0.f);
        v.z = fmaxf(v.z, 0.f); v.w = fmaxf(v.w, 0.f);
    }
    ((float4*)feat)[t] = v;
}

// ---------------------------------------------------------------------------
// Context GEMM on TF32 tensor cores over len-bucketed rows, fused final:
//   out[i,c] = feat2[i,c] * (sum_{j<len[i]} feat2[label[i,j],:] @ Wr[j*256:, c]
//                            + rb[c])
// Rows processed via g_perm (sorted by context_len) so K_eff per block ~= len.
// BM=128, BN=64, BK=32, fragment-layout smem, 2 CTAs/SM target.
// ---------------------------------------------------------------------------
__global__ __launch_bounds__(256, 2) void ctx_gemm_tc_kernel(
    const float* __restrict__ feat,
    const int* __restrict__ perm,      // [M] rows sorted by clen
    const int* __restrict__ label,     // [M, 8]
    const int* __restrict__ clen,      // [M]
    const float* __restrict__ Wr,      // [2048, 256]
    const float* __restrict__ rb,      // [256]
    float* __restrict__ out, int M)
{
    __shared__ uint32_t As[4096];       // 128m x 32k
    __shared__ uint32_t Bs[2048];       // 32k x 64n
    __shared__ int s_label[128][MAXCTX];
    __shared__ int s_len[128];
    __shared__ int s_row[128];
    __shared__ int s_maxlen;

    const int brow = blockIdx.x * 128;
    const int bcol = blockIdx.y * 64;
    const int tid  = threadIdx.x;
    const int lane = tid & 31;
    const int warp = tid >> 5;
    const int g    = lane >> 2;
    const int tig  = lane & 3;
    const int wm   = warp & 3;
    const int wn   = warp >> 2;

    // --- stage per-row metadata (through permutation) ---
    if (tid < 128) {
        int gi = brow + tid;
        int row = (gi < M) ? perm[gi] : -1;
        s_row[tid] = row;
        s_len[tid] = (row >= 0) ? clen[row] : 0;
    }
    __syncthreads();
    for (int i = tid; i < 128 * MAXCTX; i += 256) {
        int r = i >> 3, j = i & 7;
        int row = s_row[r];
        s_label[r][j] = (row >= 0) ? label[(size_t)row * MAXCTX + j] : 0;
    }
    if (warp == 0) {
        int v = max(max(s_len[lane], s_len[lane + 32]),
                    max(s_len[lane + 64], s_len[lane + 96]));
        #pragma unroll
        for (int o = 16; o; o >>= 1) v = max(v, __shfl_xor_sync(0xffffffffu, v, o));
        if (lane == 0) s_maxlen = v;
    }
    __syncthreads();
    const int K_eff = s_maxlen * 256;

    float acc[2][4][4];
    #pragma unroll
    for (int i = 0; i < 2; ++i)
        #pragma unroll
        for (int j = 0; j < 4; ++j)
            #pragma unroll
            for (int c = 0; c < 4; ++c) acc[i][j][c] = 0.f;

    const int lm  = tid >> 1;
    const int lkb = (tid & 1) * 16;
    const int bkk = tid >> 3;
    const int bnb = (tid & 7) * 8;

    float4 rA[4], rB[2];

    auto loadTiles = [&](int k0) {
        const int j   = k0 >> 8;            // context slot
        const int kc0 = (k0 & 255) + lkb;
        const int L   = s_len[lm];
        const float* abase = feat + (size_t)s_label[lm][j] * HDIM + kc0;
        #pragma unroll
        for (int it = 0; it < 4; ++it)
            rA[it] = (j < L) ? *(const float4*)(abase + it * 4)
                             : make_float4(0.f, 0.f, 0.f, 0.f);
        const float* bbase = Wr + (size_t)(k0 + bkk) * HDIM + bcol + bnb;
        rB[0] = *(const float4*)bbase;
        rB[1] = *(const float4*)(bbase + 4);
    };

    auto storeTiles = [&]() {
        float av[16] = {rA[0].x, rA[0].y, rA[0].z, rA[0].w,
                        rA[1].x, rA[1].y, rA[1].z, rA[1].w,
                        rA[2].x, rA[2].y, rA[2].z, rA[2].w,
                        rA[3].x, rA[3].y, rA[3].z, rA[3].w};
        int mt = lm >> 4, r = lm & 15;
        #pragma unroll
        for (int o = 0; o < 16; ++o) {
            int k = lkb + o, ks = k >> 3, kk = k & 7;
            int w = ((mt * 4 + ks) * 32 + (r & 7) * 4 + (kk & 3)) * 4
                    + (kk >> 2) * 2 + (r >> 3);
            As[w] = f2tf(av[o]);
        }
        float bv[8] = {rB[0].x, rB[0].y, rB[0].z, rB[0].w,
                       rB[1].x, rB[1].y, rB[1].z, rB[1].w};
        int ks = bkk >> 3, kk = bkk & 7, t4 = kk & 3, h = kk >> 2;
        #pragma unroll
        for (int o = 0; o < 8; ++o) {
            int n = bnb + o, nt = n >> 3, g2 = n & 7;
            int w = (((nt * 4 + ks) * 4 + t4) * 8 + g2) * 2 + h;
            Bs[w] = f2tf(bv[o]);
        }
    };

    if (K_eff > 0) {
        loadTiles(0);
        storeTiles();
        __syncthreads();

        for (int k0 = 0; k0 < K_eff; k0 += 32) {
            bool more = (k0 + 32) < K_eff;
            if (more) loadTiles(k0 + 32);

            #pragma unroll
            for (int ks = 0; ks < 4; ++ks) {
                uint32_t af[2][4], bf[4][2];
                #pragma unroll
                for (int i = 0; i < 2; ++i) {
                    int base = (((wm * 2 + i) * 4 + ks) * 32 + lane) * 4;
                    uint4 a4 = *(const uint4*)&As[base];
                    af[i][0] = a4.x; af[i][1] = a4.y; af[i][2] = a4.z; af[i][3] = a4.w;
                }
                #pragma unroll
                for (int jn = 0; jn < 4; ++jn) {
                    int base = ((((wn * 4 + jn) * 4 + ks) * 4 + tig) * 8 + g) * 2;
                    uint2 b2 = *(const uint2*)&Bs[base];
                    bf[jn][0] = b2.x; bf[jn][1] = b2.y;
                }
                #pragma unroll
                for (int i = 0; i < 2; ++i)
                    #pragma unroll
                    for (int jn = 0; jn < 4; ++jn)
                        mma_tf32(acc[i][jn], af[i], bf[jn]);
            }
            __syncthreads();
            if (more) { storeTiles(); __syncthreads(); }
        }
    }

    // fused epilogue through permutation: out[row] = feat2[row] * (acc + rb)
    #pragma unroll
    for (int i = 0; i < 2; ++i) {
        int lr0 = (wm * 2 + i) * 16 + g;
        int lr1 = lr0 + 8;
        int row0 = s_row[lr0];
        int row1 = s_row[lr1];
        #pragma unroll
        for (int jn = 0; jn < 4; ++jn) {
            int c = bcol + (wn * 4 + jn) * 8 + tig * 2;
            float2 bv = *(const float2*)(rb + c);
            if (row0 >= 0) {
                float2 fv = *(const float2*)(feat + (size_t)row0 * HDIM + c);
                float2 o;
                o.x = (acc[i][jn][0] + bv.x) * fv.x;
                o.y = (acc[i][jn][1] + bv.y) * fv.y;
                *(float2*)(out + (size_t)row0 * HDIM + c) = o;
            }
            if (row1 >= 0) {
                float2 fv = *(const float2*)(feat + (size_t)row1 * HDIM + c);
                float2 o;
                o.x = (acc[i][jn][2] + bv.x) * fv.x;
                o.y = (acc[i][jn][3] + bv.y) * fv.y;
                *(float2*)(out + (size_t)row1 * HDIM + c) = o;
            }
        }
    }
}

// ---------------------------------------------------------------------------
// Launch
// ---------------------------------------------------------------------------
extern "C" void kernel_launch(void* const* d_in, const int* in_sizes, int n_in,
                              void* d_out, int out_size)
{
    const float* x     = (const float*)d_in[0];
    const int*   ei    = (const int*)  d_in[1];   // [2, E]: src row then dst row
    const int*   label = (const int*)  d_in[2];
    const int*   clen  = (const int*)  d_in[3];
    const float* gW    = (const float*)d_in[4];
    const float* gb    = (const float*)d_in[5];
    const float* rW    = (const float*)d_in[6];
    const float* rb    = (const float*)d_in[7];
    float*       out   = (float*)d_out;

    const int N = in_sizes[3];
    const int E = in_sizes[1] / 2;
    const int* src = ei;
    const int* dst = ei + E;

    float *hp, *agg, *feat, *inv;
    int *perm;
    cudaGetSymbolAddress((void**)&hp,   g_h);
    cudaGetSymbolAddress((void**)&agg,  g_agg);
    cudaGetSymbolAddress((void**)&feat, g_feat);
    cudaGetSymbolAddress((void**)&inv,  g_inv);
    cudaGetSymbolAddress((void**)&perm, g_perm);

    const int total4 = N * (HDIM / 4);
    const int TPB = 256;
    dim3 gemm_grid((N + 127) / 128, 4);   // BN=64 -> 4 column blocks

    // --- normalization + length bucketing (tiny kernels) ---
    deg_init_kernel<<<(N + TPB - 1) / TPB, TPB>>>(inv, N);
    deg_count_kernel<<<(E + TPB - 1) / TPB, TPB>>>(dst, inv, E);
    inv_sqrt_kernel<<<(N + TPB - 1) / TPB, TPB>>>(inv, N);
    bucket_init_kernel<<<1, 32>>>();
    bucket_hist_kernel<<<(N + TPB - 1) / TPB, TPB>>>(clen, N);
    bucket_scan_kernel<<<1, 1>>>();
    bucket_scatter_kernel<<<(N + TPB - 1) / TPB, TPB>>>(clen, N);

    // --- GCN layer 1: feat1 = relu(inv*scatter(h') + b), h' = (x@W)*inv ---
    gcn_gemm_tc_kernel<<<gemm_grid, TPB>>>(x, gW, inv, hp, agg, N);
    scatter_kernel<<<(E * 32 + TPB - 1) / TPB, TPB>>>(hp, src, dst, agg, E);
    epilogue_kernel<true><<<(total4 + TPB - 1) / TPB, TPB>>>(agg, inv, gb, feat, total4);

    // --- GCN layer 2 ---
    gcn_gemm_tc_kernel<<<gemm_grid, TPB>>>(feat, gW, inv, hp, agg, N);
    scatter_kernel<<<(E * 32 + TPB - 1) / TPB, TPB>>>(hp, src, dst, agg, E);
    epilogue_kernel<false><<<(total4 + TPB - 1) / TPB, TPB>>>(agg, inv, gb, feat, total4);

    // --- bucketed context gather-GEMM, fused final product ---
    ctx_gemm_tc_kernel<<<gemm_grid, TPB>>>(feat, perm, label, clen, rW, rb, out, N);
}

// round 11
// speedup vs baseline: 1.5905x; 1.5037x over previous
#include <cuda_runtime.h>
#include <cstdint>

#define N_MAX   50000
#define HDIM    256
#define E_MAX   800000
#define MAXCTX  8

// ---------------------------------------------------------------------------
// Scratch (device globals -- no allocation allowed in kernel_launch)
// ---------------------------------------------------------------------------
__device__ float g_h[N_MAX * HDIM];     // h' = (A @ W) * inv[row]
__device__ float g_agg[N_MAX * HDIM];   // scatter accumulator
__device__ float g_feat[N_MAX * HDIM];  // layer output (feat1 then feat2)
__device__ float g_inv[N_MAX];          // deg, then rsqrt(deg)
__device__ int   g_bcnt[MAXCTX];        // bucket counts (clen in 0..7)
__device__ int   g_boff[MAXCTX];        // bucket offsets (mutated by scatter)
__device__ int   g_perm[N_MAX];         // rows sorted by context_len

// ---------------------------------------------------------------------------
// Degree / normalization
// ---------------------------------------------------------------------------
__global__ void deg_init_kernel(float* deg, int n) {
    int i = blockIdx.x * blockDim.x + threadIdx.x;
    if (i < n) deg[i] = 1.0f;  // self loop
}

__global__ void deg_count_kernel(const int* __restrict__ dst, float* deg, int e) {
    int i = blockIdx.x * blockDim.x + threadIdx.x;
    if (i < e) atomicAdd(&deg[dst[i]], 1.0f);
}

__global__ void inv_sqrt_kernel(float* deg, int n) {
    int i = blockIdx.x * blockDim.x + threadIdx.x;
    if (i < n) deg[i] = rsqrtf(deg[i]);
}

// ---------------------------------------------------------------------------
// Bucket sort of rows by context_len (8 bins) — validated R10
// ---------------------------------------------------------------------------
__global__ void bucket_init_kernel() {
    if (threadIdx.x < MAXCTX) g_bcnt[threadIdx.x] = 0;
}
__global__ void bucket_hist_kernel(const int* __restrict__ clen, int n) {
    int i = blockIdx.x * blockDim.x + threadIdx.x;
    if (i < n) atomicAdd(&g_bcnt[clen[i]], 1);
}
__global__ void bucket_scan_kernel() {
    if (threadIdx.x == 0) {
        int acc = 0;
        for (int b = 0; b < MAXCTX; ++b) { g_boff[b] = acc; acc += g_bcnt[b]; }
    }
}
__global__ void bucket_scatter_kernel(const int* __restrict__ clen, int n) {
    int i = blockIdx.x * blockDim.x + threadIdx.x;
    if (i < n) {
        int p = atomicAdd(&g_boff[clen[i]], 1);
        g_perm[p] = i;
    }
}

// ---------------------------------------------------------------------------
// SGEMM (fp32 SIMT, proven 169us): writes hprime = (A@W)*inv and agg = hprime
// BM=128, BN=128, BK=16, 256 threads, 8x8 per thread
// ---------------------------------------------------------------------------
__global__ __launch_bounds__(256) void sgemm_fused_kernel(
    const float* __restrict__ A, const float* __restrict__ B,
    const float* __restrict__ inv,
    float* __restrict__ hprime, float* __restrict__ agg, int M)
{
    const int K = 256;
    __shared__ float As[16][128];   // transposed: As[k][m]
    __shared__ float Bs[16][128];

    const int block_row = blockIdx.x * 128;
    const int block_col = blockIdx.y * 128;
    const int tid = threadIdx.x;
    const int tr = tid >> 4;            // 0..15
    const int tc = tid & 15;            // 0..15

    const int a_row0 = tid >> 2;        // 0..63
    const int a_col  = (tid & 3) * 4;   // 0,4,8,12
    const int b_row0 = tid >> 5;        // 0..7
    const int b_col  = (tid & 31) * 4;  // 0..124

    float acc[8][8] = {};

    for (int k0 = 0; k0 < K; k0 += 16) {
        #pragma unroll
        for (int it = 0; it < 2; ++it) {
            int m = a_row0 + it * 64;
            int gr = block_row + m;
            float4 v = make_float4(0.f, 0.f, 0.f, 0.f);
            if (gr < M) v = *(const float4*)(A + (size_t)gr * K + k0 + a_col);
            As[a_col + 0][m] = v.x;
            As[a_col + 1][m] = v.y;
            As[a_col + 2][m] = v.z;
            As[a_col + 3][m] = v.w;
        }
        #pragma unroll
        for (int it = 0; it < 2; ++it) {
            int kk = b_row0 + it * 8;
            *(float4*)&Bs[kk][b_col] =
                *(const float4*)(B + (size_t)(k0 + kk) * 256 + block_col + b_col);
        }
        __syncthreads();

        #pragma unroll
        for (int kk = 0; kk < 16; ++kk) {
            float4 a0 = *(const float4*)&As[kk][tr * 8];
            float4 a1 = *(const float4*)&As[kk][tr * 8 + 4];
            float4 b0 = *(const float4*)&Bs[kk][tc * 8];
            float4 b1 = *(const float4*)&Bs[kk][tc * 8 + 4];
            float ar[8] = {a0.x, a0.y, a0.z, a0.w, a1.x, a1.y, a1.z, a1.w};
            float br[8] = {b0.x, b0.y, b0.z, b0.w, b1.x, b1.y, b1.z, b1.w};
            #pragma unroll
            for (int i = 0; i < 8; ++i)
                #pragma unroll
                for (int j = 0; j < 8; ++j)
                    acc[i][j] += ar[i] * br[j];
        }
        __syncthreads();
    }

    #pragma unroll
    for (int i = 0; i < 8; ++i) {
        int gr = block_row + tr * 8 + i;
        if (gr < M) {
            float iv = inv[gr];
            #pragma unroll
            for (int j = 0; j < 8; j += 4) {
                float4 o = make_float4(acc[i][j] * iv, acc[i][j+1] * iv,
                                       acc[i][j+2] * iv, acc[i][j+3] * iv);
                size_t off = (size_t)gr * 256 + block_col + tc * 8 + j;
                *(float4*)(hprime + off) = o;
                *(float4*)(agg    + off) = o;
            }
        }
    }
}

// ---------------------------------------------------------------------------
// Edge scatter: agg[dst,:] += hprime[src,:]   (pure vectorized reductions)
// ---------------------------------------------------------------------------
__global__ void scatter_kernel(const float* __restrict__ hp,
                               const int* __restrict__ src,
                               const int* __restrict__ dst,
                               float* __restrict__ agg, int e)
{
    int warp = (blockIdx.x * blockDim.x + threadIdx.x) >> 5;
    int lane = threadIdx.x & 31;
    if (warp >= e) return;
    int s = __ldg(&src[warp]);
    int d = __ldg(&dst[warp]);
    const float4* hpp = (const float4*)(hp + (size_t)s * 256);
    float* ap = agg + (size_t)d * 256;
    #pragma unroll
    for (int it = 0; it < 2; ++it) {
        int idx = lane + it * 32;
        float4 v = hpp[idx];
        asm volatile("red.global.add.v4.f32 [%0], {%1, %2, %3, %4};"
                     :: "l"(ap + (size_t)idx * 4),
                        "f"(v.x), "f"(v.y), "f"(v.z), "f"(v.w)
                     : "memory");
    }
}

// ---------------------------------------------------------------------------
// Epilogue: feat = agg * inv[row] + b, optional relu
// ---------------------------------------------------------------------------
template <bool RELU>
__global__ void epilogue_kernel(const float* __restrict__ agg,
                                const float* __restrict__ inv,
                                const float* __restrict__ b,
                                float* __restrict__ feat, int total4)
{
    int t = blockIdx.x * blockDim.x + threadIdx.x;
    if (t >= total4) return;
    int row = t >> 6;
    int c4  = t & 63;
    float iv = inv[row];
    float4 v  = ((const float4*)agg)[t];
    float4 bb = ((const float4*)b)[c4];
    v.x = v.x * iv + bb.x; v.y = v.y * iv + bb.y;
    v.z = v.z * iv + bb.z; v.w = v.w * iv + bb.w;
    if (RELU) {
        v.x = fmaxf(v.x, 0.f); v.y = fmaxf(v.y, 0.f);
        v.z = fmaxf(v.z, 0.f); v.w = fmaxf(v.w, 0.f);
    }
    ((float4*)feat)[t] = v;
}

// ---------------------------------------------------------------------------
// TF32 helpers
// ---------------------------------------------------------------------------
__device__ __forceinline__ uint32_t f2tf(float x) {
    uint32_t r;
    asm("cvt.rna.tf32.f32 %0, %1;" : "=r"(r) : "f"(x));
    return r;
}

__device__ __forceinline__ void mma_tf32(float d[4], const uint32_t a[4],
                                         const uint32_t b[2]) {
    asm volatile(
        "mma.sync.aligned.m16n8k8.row.col.f32.tf32.tf32.f32 "
        "{%0,%1,%2,%3}, {%4,%5,%6,%7}, {%8,%9}, {%0,%1,%2,%3};"
        : "+f"(d[0]), "+f"(d[1]), "+f"(d[2]), "+f"(d[3])
        : "r"(a[0]), "r"(a[1]), "r"(a[2]), "r"(a[3]),
          "r"(b[0]), "r"(b[1]));
}

// ---------------------------------------------------------------------------
// Context GEMM on TF32 tensor cores (R6 layout, part of the 1393us composite)
// plus length-bucketed row permutation (validated R10):
//   out[row,c] = feat2[row,c] * ( sum_{j<len[row]} feat2[label[row,j],:]
//                                 @ Wr[j*256:, c]  + rb[c] )
// BM=128, BN=128, BK=32, 8 warps (2x4), warp tile 64x32 via m16n8k8.
// ---------------------------------------------------------------------------
__global__ __launch_bounds__(256, 1) void ctx_gemm_tc_kernel(
    const float* __restrict__ feat,
    const int* __restrict__ perm,      // [M] rows sorted by clen
    const int* __restrict__ label,     // [M, 8]
    const int* __restrict__ clen,      // [M]
    const float* __restrict__ Wr,      // [2048, 256]
    const float* __restrict__ rb,      // [256]
    float* __restrict__ out, int M)
{
    __shared__ uint32_t As[32][132];    // logical A[k][m], padded
    __shared__ uint32_t Bsp[16][260];   // B k-pair interleaved
    __shared__ int s_label[128][MAXCTX];
    __shared__ int s_len[128];
    __shared__ int s_row[128];
    __shared__ int s_maxlen;

    const int brow = blockIdx.x * 128;
    const int bcol = blockIdx.y * 128;
    const int tid  = threadIdx.x;
    const int lane = tid & 31;
    const int warp = tid >> 5;
    const int g    = lane >> 2;   // 0..7
    const int tig  = lane & 3;    // 0..3
    const int wm   = warp & 1;    // warp row (2)
    const int wn   = warp >> 1;   // warp col (4)

    // --- stage per-row metadata through the permutation ---
    if (tid < 128) {
        int gi = brow + tid;
        int row = (gi < M) ? perm[gi] : -1;
        s_row[tid] = row;
        s_len[tid] = (row >= 0) ? clen[row] : 0;
    }
    __syncthreads();
    for (int i = tid; i < 128 * MAXCTX; i += 256) {
        int r = i >> 3, j = i & 7;
        int row = s_row[r];
        s_label[r][j] = (row >= 0) ? label[(size_t)row * MAXCTX + j] : 0;
    }
    if (warp == 0) {
        int v = max(max(s_len[lane], s_len[lane + 32]),
                    max(s_len[lane + 64], s_len[lane + 96]));
        #pragma unroll
        for (int o = 16; o; o >>= 1) v = max(v, __shfl_xor_sync(0xffffffffu, v, o));
        if (lane == 0) s_maxlen = v;
    }
    __syncthreads();
    const int K_eff = s_maxlen * 256;   // bucketed: ~= len(bucket)*256

    float acc[4][4][4];
    #pragma unroll
    for (int i = 0; i < 4; ++i)
        #pragma unroll
        for (int j = 0; j < 4; ++j)
            #pragma unroll
            for (int c = 0; c < 4; ++c) acc[i][j][c] = 0.f;

    // loader indices
    const int lm  = tid >> 1;          // A row 0..127
    const int lkb = (tid & 1) * 16;    // A k-base 0 / 16
    const int bkk = tid & 31;          // B k-row 0..31
    const int bnb = (tid >> 5) * 16;   // B n-base

    float4 rA[4], rB[4];

    auto loadTiles = [&](int k0) {
        const int j   = k0 >> 8;            // context slot (constant in a tile)
        const int kc0 = (k0 & 255) + lkb;
        const int L   = s_len[lm];
        const float* abase = feat + (size_t)s_label[lm][j] * HDIM + kc0;
        #pragma unroll
        for (int it = 0; it < 4; ++it) {
            float4 v = make_float4(0.f, 0.f, 0.f, 0.f);
            if (j < L) v = *(const float4*)(abase + it * 4);
            rA[it] = v;
        }
        const float* bbase = Wr + (size_t)(k0 + bkk) * HDIM + bcol + bnb;
        #pragma unroll
        for (int it = 0; it < 4; ++it)
            rB[it] = *(const float4*)(bbase + it * 4);
    };

    const int bprow = (bkk >> 3) * 4 + (bkk & 3);
    const int bkh   = (bkk >> 2) & 1;

    auto storeTiles = [&]() {
        #pragma unroll
        for (int it = 0; it < 4; ++it) {
            int k = lkb + it * 4;
            As[k + 0][lm] = f2tf(rA[it].x);
            As[k + 1][lm] = f2tf(rA[it].y);
            As[k + 2][lm] = f2tf(rA[it].z);
            As[k + 3][lm] = f2tf(rA[it].w);
        }
        #pragma unroll
        for (int it = 0; it < 4; ++it) {
            int n = bnb + it * 4;
            Bsp[bprow][2 * (n + 0) + bkh] = f2tf(rB[it].x);
            Bsp[bprow][2 * (n + 1) + bkh] = f2tf(rB[it].y);
            Bsp[bprow][2 * (n + 2) + bkh] = f2tf(rB[it].z);
            Bsp[bprow][2 * (n + 3) + bkh] = f2tf(rB[it].w);
        }
    };

    if (K_eff > 0) {
        loadTiles(0);
        storeTiles();
        __syncthreads();

        for (int k0 = 0; k0 < K_eff; k0 += 32) {
            bool more = (k0 + 32) < K_eff;
            if (more) loadTiles(k0 + 32);   // overlap with compute below

            #pragma unroll
            for (int ks = 0; ks < 4; ++ks) {
                uint32_t af[4][4], bf[4][2];
                #pragma unroll
                for (int i = 0; i < 4; ++i) {
                    int mb = wm * 64 + i * 16 + g;
                    af[i][0] = As[ks * 8 + tig    ][mb];
                    af[i][1] = As[ks * 8 + tig    ][mb + 8];
                    af[i][2] = As[ks * 8 + tig + 4][mb];
                    af[i][3] = As[ks * 8 + tig + 4][mb + 8];
                }
                #pragma unroll
                for (int jn = 0; jn < 4; ++jn) {
                    int n = wn * 32 + jn * 8 + g;
                    uint2 bb = *(const uint2*)&Bsp[ks * 4 + tig][2 * n];
                    bf[jn][0] = bb.x;
                    bf[jn][1] = bb.y;
                }
                #pragma unroll
                for (int i = 0; i < 4; ++i)
                    #pragma unroll
                    for (int jn = 0; jn < 4; ++jn)
                        mma_tf32(acc[i][jn], af[i], bf[jn]);
            }
            __syncthreads();
            if (more) { storeTiles(); __syncthreads(); }
        }
    }

    // fused epilogue through permutation: out[row] = feat2[row] * (acc + rb)
    #pragma unroll
    for (int i = 0; i < 4; ++i) {
        int lr0 = wm * 64 + i * 16 + g;
        int lr1 = lr0 + 8;
        int row0 = s_row[lr0];
        int row1 = s_row[lr1];
        #pragma unroll
        for (int jn = 0; jn < 4; ++jn) {
            int c = bcol + wn * 32 + jn * 8 + tig * 2;
            float2 bv = *(const float2*)(rb + c);
            if (row0 >= 0) {
                float2 fv = *(const float2*)(feat + (size_t)row0 * HDIM + c);
                float2 o;
                o.x = (acc[i][jn][0] + bv.x) * fv.x;
                o.y = (acc[i][jn][1] + bv.y) * fv.y;
                *(float2*)(out + (size_t)row0 * HDIM + c) = o;
            }
            if (row1 >= 0) {
                float2 fv = *(const float2*)(feat + (size_t)row1 * HDIM + c);
                float2 o;
                o.x = (acc[i][jn][2] + bv.x) * fv.x;
                o.y = (acc[i][jn][3] + bv.y) * fv.y;
                *(float2*)(out + (size_t)row1 * HDIM + c) = o;
            }
        }
    }
}

// ---------------------------------------------------------------------------
// Launch
// ---------------------------------------------------------------------------
extern "C" void kernel_launch(void* const* d_in, const int* in_sizes, int n_in,
                              void* d_out, int out_size)
{
    const float* x     = (const float*)d_in[0];
    const int*   ei    = (const int*)  d_in[1];   // [2, E]: src row then dst row
    const int*   label = (const int*)  d_in[2];
    const int*   clen  = (const int*)  d_in[3];
    const float* gW    = (const float*)d_in[4];
    const float* gb    = (const float*)d_in[5];
    const float* rW    = (const float*)d_in[6];
    const float* rb    = (const float*)d_in[7];
    float*       out   = (float*)d_out;

    const int N = in_sizes[3];
    const int E = in_sizes[1] / 2;
    const int* src = ei;
    const int* dst = ei + E;

    float *hp, *agg, *feat, *inv;
    int *perm;
    cudaGetSymbolAddress((void**)&hp,   g_h);
    cudaGetSymbolAddress((void**)&agg,  g_agg);
    cudaGetSymbolAddress((void**)&feat, g_feat);
    cudaGetSymbolAddress((void**)&inv,  g_inv);
    cudaGetSymbolAddress((void**)&perm, g_perm);

    const int total4 = N * (HDIM / 4);
    const int TPB = 256;
    dim3 gemm_grid((N + 127) / 128, 2);   // BN=128 -> 2 column blocks

    // --- normalization + length bucketing ---
    deg_init_kernel<<<(N + TPB - 1) / TPB, TPB>>>(inv, N);
    deg_count_kernel<<<(E + TPB - 1) / TPB, TPB>>>(dst, inv, E);
    inv_sqrt_kernel<<<(N + TPB - 1) / TPB, TPB>>>(inv, N);
    bucket_init_kernel<<<1, 32>>>();
    bucket_hist_kernel<<<(N + TPB - 1) / TPB, TPB>>>(clen, N);
    bucket_scan_kernel<<<1, 1>>>();
    bucket_scatter_kernel<<<(N + TPB - 1) / TPB, TPB>>>(clen, N);

    // --- GCN layer 1: feat1 = relu(inv*scatter(h') + b), h' = (x@W)*inv ---
    sgemm_fused_kernel<<<gemm_grid, TPB>>>(x, gW, inv, hp, agg, N);
    scatter_kernel<<<(E * 32 + TPB - 1) / TPB, TPB>>>(hp, src, dst, agg, E);
    epilogue_kernel<true><<<(total4 + TPB - 1) / TPB, TPB>>>(agg, inv, gb, feat, total4);

    // --- GCN layer 2 ---
    sgemm_fused_kernel<<<gemm_grid, TPB>>>(feat, gW, inv, hp, agg, N);
    scatter_kernel<<<(E * 32 + TPB - 1) / TPB, TPB>>>(hp, src, dst, agg, E);
    epilogue_kernel<false><<<(total4 + TPB - 1) / TPB, TPB>>>(agg, inv, gb, feat, total4);

    // --- bucketed context gather-GEMM on TF32 tensor cores, fused final ---
    ctx_gemm_tc_kernel<<<gemm_grid, TPB>>>(feat, perm, label, clen, rW, rb, out, N);
}

// round 12
// speedup vs baseline: 1.5931x; 1.0016x over previous
#include <cuda_runtime.h>
#include <cstdint>

#define N_MAX   50000
#define HDIM    256
#define E_MAX   800000
#define MAXCTX  8

// ---------------------------------------------------------------------------
// Scratch (device globals -- no allocation allowed in kernel_launch)
// ---------------------------------------------------------------------------
__device__ float g_h[N_MAX * HDIM];     // h' = (A @ W) * inv[row]
__device__ float g_agg[N_MAX * HDIM];   // scatter accumulator
__device__ float g_feat[N_MAX * HDIM];  // layer output (feat1 then feat2)
__device__ float g_inv[N_MAX];          // deg, then rsqrt(deg)
__device__ int   g_bcnt[MAXCTX];        // bucket counts (clen in 0..7)
__device__ int   g_boff[MAXCTX];        // bucket offsets (mutated by scatter)
__device__ int   g_perm[N_MAX];         // rows sorted by context_len

// ---------------------------------------------------------------------------
// Degree / normalization
// ---------------------------------------------------------------------------
__global__ void deg_init_kernel(float* deg, int n) {
    int i = blockIdx.x * blockDim.x + threadIdx.x;
    if (i < n) deg[i] = 1.0f;  // self loop
}

__global__ void deg_count_kernel(const int* __restrict__ dst, float* deg, int e) {
    int i = blockIdx.x * blockDim.x + threadIdx.x;
    if (i < e) atomicAdd(&deg[dst[i]], 1.0f);
}

__global__ void inv_sqrt_kernel(float* deg, int n) {
    int i = blockIdx.x * blockDim.x + threadIdx.x;
    if (i < n) deg[i] = rsqrtf(deg[i]);
}

// ---------------------------------------------------------------------------
// Bucket sort of rows by context_len (8 bins) — validated R10
// ---------------------------------------------------------------------------
__global__ void bucket_init_kernel() {
    if (threadIdx.x < MAXCTX) g_bcnt[threadIdx.x] = 0;
}
__global__ void bucket_hist_kernel(const int* __restrict__ clen, int n) {
    int i = blockIdx.x * blockDim.x + threadIdx.x;
    if (i < n) atomicAdd(&g_bcnt[clen[i]], 1);
}
__global__ void bucket_scan_kernel() {
    if (threadIdx.x == 0) {
        int acc = 0;
        for (int b = 0; b < MAXCTX; ++b) { g_boff[b] = acc; acc += g_bcnt[b]; }
    }
}
__global__ void bucket_scatter_kernel(const int* __restrict__ clen, int n) {
    int i = blockIdx.x * blockDim.x + threadIdx.x;
    if (i < n) {
        int p = atomicAdd(&g_boff[clen[i]], 1);
        g_perm[p] = i;
    }
}

// ---------------------------------------------------------------------------
// SGEMM (fp32 SIMT, proven 169us): writes hprime = (A@W)*inv and agg = hprime
// BM=128, BN=128, BK=16, 256 threads, 8x8 per thread
// ---------------------------------------------------------------------------
__global__ __launch_bounds__(256) void sgemm_fused_kernel(
    const float* __restrict__ A, const float* __restrict__ B,
    const float* __restrict__ inv,
    float* __restrict__ hprime, float* __restrict__ agg, int M)
{
    const int K = 256;
    __shared__ float As[16][128];   // transposed: As[k][m]
    __shared__ float Bs[16][128];

    const int block_row = blockIdx.x * 128;
    const int block_col = blockIdx.y * 128;
    const int tid = threadIdx.x;
    const int tr = tid >> 4;            // 0..15
    const int tc = tid & 15;            // 0..15

    const int a_row0 = tid >> 2;        // 0..63
    const int a_col  = (tid & 3) * 4;   // 0,4,8,12
    const int b_row0 = tid >> 5;        // 0..7
    const int b_col  = (tid & 31) * 4;  // 0..124

    float acc[8][8] = {};

    for (int k0 = 0; k0 < K; k0 += 16) {
        #pragma unroll
        for (int it = 0; it < 2; ++it) {
            int m = a_row0 + it * 64;
            int gr = block_row + m;
            float4 v = make_float4(0.f, 0.f, 0.f, 0.f);
            if (gr < M) v = *(const float4*)(A + (size_t)gr * K + k0 + a_col);
            As[a_col + 0][m] = v.x;
            As[a_col + 1][m] = v.y;
            As[a_col + 2][m] = v.z;
            As[a_col + 3][m] = v.w;
        }
        #pragma unroll
        for (int it = 0; it < 2; ++it) {
            int kk = b_row0 + it * 8;
            *(float4*)&Bs[kk][b_col] =
                *(const float4*)(B + (size_t)(k0 + kk) * 256 + block_col + b_col);
        }
        __syncthreads();

        #pragma unroll
        for (int kk = 0; kk < 16; ++kk) {
            float4 a0 = *(const float4*)&As[kk][tr * 8];
            float4 a1 = *(const float4*)&As[kk][tr * 8 + 4];
            float4 b0 = *(const float4*)&Bs[kk][tc * 8];
            float4 b1 = *(const float4*)&Bs[kk][tc * 8 + 4];
            float ar[8] = {a0.x, a0.y, a0.z, a0.w, a1.x, a1.y, a1.z, a1.w};
            float br[8] = {b0.x, b0.y, b0.z, b0.w, b1.x, b1.y, b1.z, b1.w};
            #pragma unroll
            for (int i = 0; i < 8; ++i)
                #pragma unroll
                for (int j = 0; j < 8; ++j)
                    acc[i][j] += ar[i] * br[j];
        }
        __syncthreads();
    }

    #pragma unroll
    for (int i = 0; i < 8; ++i) {
        int gr = block_row + tr * 8 + i;
        if (gr < M) {
            float iv = inv[gr];
            #pragma unroll
            for (int j = 0; j < 8; j += 4) {
                float4 o = make_float4(acc[i][j] * iv, acc[i][j+1] * iv,
                                       acc[i][j+2] * iv, acc[i][j+3] * iv);
                size_t off = (size_t)gr * 256 + block_col + tc * 8 + j;
                *(float4*)(hprime + off) = o;
                *(float4*)(agg    + off) = o;
            }
        }
    }
}

// ---------------------------------------------------------------------------
// Edge scatter: agg[dst,:] += hprime[src,:]   (pure vectorized reductions)
// ---------------------------------------------------------------------------
__global__ void scatter_kernel(const float* __restrict__ hp,
                               const int* __restrict__ src,
                               const int* __restrict__ dst,
                               float* __restrict__ agg, int e)
{
    int warp = (blockIdx.x * blockDim.x + threadIdx.x) >> 5;
    int lane = threadIdx.x & 31;
    if (warp >= e) return;
    int s = __ldg(&src[warp]);
    int d = __ldg(&dst[warp]);
    const float4* hpp = (const float4*)(hp + (size_t)s * 256);
    float* ap = agg + (size_t)d * 256;
    #pragma unroll
    for (int it = 0; it < 2; ++it) {
        int idx = lane + it * 32;
        float4 v = hpp[idx];
        asm volatile("red.global.add.v4.f32 [%0], {%1, %2, %3, %4};"
                     :: "l"(ap + (size_t)idx * 4),
                        "f"(v.x), "f"(v.y), "f"(v.z), "f"(v.w)
                     : "memory");
    }
}

// ---------------------------------------------------------------------------
// Epilogue: feat = agg * inv[row] + b, optional relu
// ---------------------------------------------------------------------------
template <bool RELU>
__global__ void epilogue_kernel(const float* __restrict__ agg,
                                const float* __restrict__ inv,
                                const float* __restrict__ b,
                                float* __restrict__ feat, int total4)
{
    int t = blockIdx.x * blockDim.x + threadIdx.x;
    if (t >= total4) return;
    int row = t >> 6;
    int c4  = t & 63;
    float iv = inv[row];
    float4 v  = ((const float4*)agg)[t];
    float4 bb = ((const float4*)b)[c4];
    v.x = v.x * iv + bb.x; v.y = v.y * iv + bb.y;
    v.z = v.z * iv + bb.z; v.w = v.w * iv + bb.w;
    if (RELU) {
        v.x = fmaxf(v.x, 0.f); v.y = fmaxf(v.y, 0.f);
        v.z = fmaxf(v.z, 0.f); v.w = fmaxf(v.w, 0.f);
    }
    ((float4*)feat)[t] = v;
}

// ---------------------------------------------------------------------------
// TF32 helpers
// ---------------------------------------------------------------------------
__device__ __forceinline__ uint32_t f2tf(float x) {
    uint32_t r;
    asm("cvt.rna.tf32.f32 %0, %1;" : "=r"(r) : "f"(x));
    return r;
}

__device__ __forceinline__ void mma_tf32(float d[4], const uint32_t a[4],
                                         const uint32_t b[2]) {
    asm volatile(
        "mma.sync.aligned.m16n8k8.row.col.f32.tf32.tf32.f32 "
        "{%0,%1,%2,%3}, {%4,%5,%6,%7}, {%8,%9}, {%0,%1,%2,%3};"
        : "+f"(d[0]), "+f"(d[1]), "+f"(d[2]), "+f"(d[3])
        : "r"(a[0]), "r"(a[1]), "r"(a[2]), "r"(a[3]),
          "r"(b[0]), "r"(b[1]));
}

// ---------------------------------------------------------------------------
// Context GEMM on TF32 tensor cores (R6 layout, part of the 1393us composite)
// plus length-bucketed row permutation (validated R10):
//   out[row,c] = feat2[row,c] * ( sum_{j<len[row]} feat2[label[row,j],:]
//                                 @ Wr[j*256:, c]  + rb[c] )
// BM=128, BN=128, BK=32, 8 warps (2x4), warp tile 64x32 via m16n8k8.
// ---------------------------------------------------------------------------
__global__ __launch_bounds__(256, 1) void ctx_gemm_tc_kernel(
    const float* __restrict__ feat,
    const int* __restrict__ perm,      // [M] rows sorted by clen
    const int* __restrict__ label,     // [M, 8]
    const int* __restrict__ clen,      // [M]
    const float* __restrict__ Wr,      // [2048, 256]
    const float* __restrict__ rb,      // [256]
    float* __restrict__ out, int M)
{
    __shared__ uint32_t As[32][132];    // logical A[k][m], padded
    __shared__ uint32_t Bsp[16][260];   // B k-pair interleaved
    __shared__ int s_label[128][MAXCTX];
    __shared__ int s_len[128];
    __shared__ int s_row[128];
    __shared__ int s_maxlen;

    const int brow = blockIdx.x * 128;
    const int bcol = blockIdx.y * 128;
    const int tid  = threadIdx.x;
    const int lane = tid & 31;
    const int warp = tid >> 5;
    const int g    = lane >> 2;   // 0..7
    const int tig  = lane & 3;    // 0..3
    const int wm   = warp & 1;    // warp row (2)
    const int wn   = warp >> 1;   // warp col (4)

    // --- stage per-row metadata through the permutation ---
    if (tid < 128) {
        int gi = brow + tid;
        int row = (gi < M) ? perm[gi] : -1;
        s_row[tid] = row;
        s_len[tid] = (row >= 0) ? clen[row] : 0;
    }
    __syncthreads();
    for (int i = tid; i < 128 * MAXCTX; i += 256) {
        int r = i >> 3, j = i & 7;
        int row = s_row[r];
        s_label[r][j] = (row >= 0) ? label[(size_t)row * MAXCTX + j] : 0;
    }
    if (warp == 0) {
        int v = max(max(s_len[lane], s_len[lane + 32]),
                    max(s_len[lane + 64], s_len[lane + 96]));
        #pragma unroll
        for (int o = 16; o; o >>= 1) v = max(v, __shfl_xor_sync(0xffffffffu, v, o));
        if (lane == 0) s_maxlen = v;
    }
    __syncthreads();
    const int K_eff = s_maxlen * 256;   // bucketed: ~= len(bucket)*256

    float acc[4][4][4];
    #pragma unroll
    for (int i = 0; i < 4; ++i)
        #pragma unroll
        for (int j = 0; j < 4; ++j)
            #pragma unroll
            for (int c = 0; c < 4; ++c) acc[i][j][c] = 0.f;

    // loader indices
    const int lm  = tid >> 1;          // A row 0..127
    const int lkb = (tid & 1) * 16;    // A k-base 0 / 16
    const int bkk = tid & 31;          // B k-row 0..31
    const int bnb = (tid >> 5) * 16;   // B n-base

    float4 rA[4], rB[4];

    auto loadTiles = [&](int k0) {
        const int j   = k0 >> 8;            // context slot (constant in a tile)
        const int kc0 = (k0 & 255) + lkb;
        const int L   = s_len[lm];
        const float* abase = feat + (size_t)s_label[lm][j] * HDIM + kc0;
        #pragma unroll
        for (int it = 0; it < 4; ++it) {
            float4 v = make_float4(0.f, 0.f, 0.f, 0.f);
            if (j < L) v = *(const float4*)(abase + it * 4);
            rA[it] = v;
        }
        const float* bbase = Wr + (size_t)(k0 + bkk) * HDIM + bcol + bnb;
        #pragma unroll
        for (int it = 0; it < 4; ++it)
            rB[it] = *(const float4*)(bbase + it * 4);
    };

    const int bprow = (bkk >> 3) * 4 + (bkk & 3);
    const int bkh   = (bkk >> 2) & 1;

    auto storeTiles = [&]() {
        #pragma unroll
        for (int it = 0; it < 4; ++it) {
            int k = lkb + it * 4;
            As[k + 0][lm] = f2tf(rA[it].x);
            As[k + 1][lm] = f2tf(rA[it].y);
            As[k + 2][lm] = f2tf(rA[it].z);
            As[k + 3][lm] = f2tf(rA[it].w);
        }
        #pragma unroll
        for (int it = 0; it < 4; ++it) {
            int n = bnb + it * 4;
            Bsp[bprow][2 * (n + 0) + bkh] = f2tf(rB[it].x);
            Bsp[bprow][2 * (n + 1) + bkh] = f2tf(rB[it].y);
            Bsp[bprow][2 * (n + 2) + bkh] = f2tf(rB[it].z);
            Bsp[bprow][2 * (n + 3) + bkh] = f2tf(rB[it].w);
        }
    };

    if (K_eff > 0) {
        loadTiles(0);
        storeTiles();
        __syncthreads();

        for (int k0 = 0; k0 < K_eff; k0 += 32) {
            bool more = (k0 + 32) < K_eff;
            if (more) loadTiles(k0 + 32);   // overlap with compute below

            #pragma unroll
            for (int ks = 0; ks < 4; ++ks) {
                uint32_t af[4][4], bf[4][2];
                #pragma unroll
                for (int i = 0; i < 4; ++i) {
                    int mb = wm * 64 + i * 16 + g;
                    af[i][0] = As[ks * 8 + tig    ][mb];
                    af[i][1] = As[ks * 8 + tig    ][mb + 8];
                    af[i][2] = As[ks * 8 + tig + 4][mb];
                    af[i][3] = As[ks * 8 + tig + 4][mb + 8];
                }
                #pragma unroll
                for (int jn = 0; jn < 4; ++jn) {
                    int n = wn * 32 + jn * 8 + g;
                    uint2 bb = *(const uint2*)&Bsp[ks * 4 + tig][2 * n];
                    bf[jn][0] = bb.x;
                    bf[jn][1] = bb.y;
                }
                #pragma unroll
                for (int i = 0; i < 4; ++i)
                    #pragma unroll
                    for (int jn = 0; jn < 4; ++jn)
                        mma_tf32(acc[i][jn], af[i], bf[jn]);
            }
            __syncthreads();
            if (more) { storeTiles(); __syncthreads(); }
        }
    }

    // fused epilogue through permutation: out[row] = feat2[row] * (acc + rb)
    #pragma unroll
    for (int i = 0; i < 4; ++i) {
        int lr0 = wm * 64 + i * 16 + g;
        int lr1 = lr0 + 8;
        int row0 = s_row[lr0];
        int row1 = s_row[lr1];
        #pragma unroll
        for (int jn = 0; jn < 4; ++jn) {
            int c = bcol + wn * 32 + jn * 8 + tig * 2;
            float2 bv = *(const float2*)(rb + c);
            if (row0 >= 0) {
                float2 fv = *(const float2*)(feat + (size_t)row0 * HDIM + c);
                float2 o;
                o.x = (acc[i][jn][0] + bv.x) * fv.x;
                o.y = (acc[i][jn][1] + bv.y) * fv.y;
                *(float2*)(out + (size_t)row0 * HDIM + c) = o;
            }
            if (row1 >= 0) {
                float2 fv = *(const float2*)(feat + (size_t)row1 * HDIM + c);
                float2 o;
                o.x = (acc[i][jn][2] + bv.x) * fv.x;
                o.y = (acc[i][jn][3] + bv.y) * fv.y;
                *(float2*)(out + (size_t)row1 * HDIM + c) = o;
            }
        }
    }
}

// ---------------------------------------------------------------------------
// Launch
// ---------------------------------------------------------------------------
extern "C" void kernel_launch(void* const* d_in, const int* in_sizes, int n_in,
                              void* d_out, int out_size)
{
    const float* x     = (const float*)d_in[0];
    const int*   ei    = (const int*)  d_in[1];   // [2, E]: src row then dst row
    const int*   label = (const int*)  d_in[2];
    const int*   clen  = (const int*)  d_in[3];
    const float* gW    = (const float*)d_in[4];
    const float* gb    = (const float*)d_in[5];
    const float* rW    = (const float*)d_in[6];
    const float* rb    = (const float*)d_in[7];
    float*       out   = (float*)d_out;

    const int N = in_sizes[3];
    const int E = in_sizes[1] / 2;
    const int* src = ei;
    const int* dst = ei + E;

    float *hp, *agg, *feat, *inv;
    int *perm;
    cudaGetSymbolAddress((void**)&hp,   g_h);
    cudaGetSymbolAddress((void**)&agg,  g_agg);
    cudaGetSymbolAddress((void**)&feat, g_feat);
    cudaGetSymbolAddress((void**)&inv,  g_inv);
    cudaGetSymbolAddress((void**)&perm, g_perm);

    const int total4 = N * (HDIM / 4);
    const int TPB = 256;
    dim3 gemm_grid((N + 127) / 128, 2);   // BN=128 -> 2 column blocks

    // --- normalization + length bucketing ---
    deg_init_kernel<<<(N + TPB - 1) / TPB, TPB>>>(inv, N);
    deg_count_kernel<<<(E + TPB - 1) / TPB, TPB>>>(dst, inv, E);
    inv_sqrt_kernel<<<(N + TPB - 1) / TPB, TPB>>>(inv, N);
    bucket_init_kernel<<<1, 32>>>();
    bucket_hist_kernel<<<(N + TPB - 1) / TPB, TPB>>>(clen, N);
    bucket_scan_kernel<<<1, 1>>>();
    bucket_scatter_kernel<<<(N + TPB - 1) / TPB, TPB>>>(clen, N);

    // --- GCN layer 1: feat1 = relu(inv*scatter(h') + b), h' = (x@W)*inv ---
    sgemm_fused_kernel<<<gemm_grid, TPB>>>(x, gW, inv, hp, agg, N);
    scatter_kernel<<<(E * 32 + TPB - 1) / TPB, TPB>>>(hp, src, dst, agg, E);
    epilogue_kernel<true><<<(total4 + TPB - 1) / TPB, TPB>>>(agg, inv, gb, feat, total4);

    // --- GCN layer 2 ---
    sgemm_fused_kernel<<<gemm_grid, TPB>>>(feat, gW, inv, hp, agg, N);
    scatter_kernel<<<(E * 32 + TPB - 1) / TPB, TPB>>>(hp, src, dst, agg, E);
    epilogue_kernel<false><<<(total4 + TPB - 1) / TPB, TPB>>>(agg, inv, gb, feat, total4);

    // --- bucketed context gather-GEMM on TF32 tensor cores, fused final ---
    ctx_gemm_tc_kernel<<<gemm_grid, TPB>>>(feat, perm, label, clen, rW, rb, out, N);
}